// round 1
// baseline (speedup 1.0000x reference)
#include <cuda_runtime.h>
#include <cuda_bf16.h>
#include <math.h>

// ---------------- problem constants ----------------
#define EDIM 1140
#define HH   1120          // H*HS
#define NH   32
#define HS   35
#define NL   36
#define VOC  45000
#define TT   128
#define BB   8
#define MM   (BB*TT)       // 1024 rows
#define FF   (4*EDIM)      // 4560
#define ATT_SCALE 0.16903085094570331f   // 35^-0.5

// ---------------- scratch (device globals; no runtime alloc) ----------------
__device__ float g_x[MM * EDIM];
__device__ float g_y[MM * EDIM];
__device__ float g_q[MM * HH];
__device__ float g_k[MM * HH];
__device__ float g_v[MM * HH];
__device__ float g_att[MM * HH];
__device__ float g_h[MM * FF];
__device__ int   g_is64;

// ---------------- index dtype detection ----------------
// indices are in [0, VOC); if stored as little-endian int64, every high 32-bit
// word is 0. If stored as int32, odd words are random indices (all-zero is
// astronomically unlikely). Scan first 512 entries' high words.
__global__ void detect_k(const int* __restrict__ raw) {
    __shared__ int any;
    if (threadIdx.x == 0) any = 0;
    __syncthreads();
    int local = 0;
    for (int i = threadIdx.x; i < 512; i += blockDim.x)
        if (raw[2 * i + 1] != 0) local = 1;
    if (local) atomicOr(&any, 1);
    __syncthreads();
    if (threadIdx.x == 0) g_is64 = any ? 0 : 1;
}

// ---------------- embedding ----------------
__global__ void embed_k(const int* __restrict__ raw,
                        const float* __restrict__ tok,
                        const float* __restrict__ pos,
                        float* __restrict__ x) {
    int r = blockIdx.x;            // 0..MM-1
    int t = r % TT;
    int idx = g_is64 ? raw[2 * r] : raw[r];
    const float* te = tok + (size_t)idx * EDIM;
    const float* pe = pos + (size_t)t * EDIM;
    float* xr = x + (size_t)r * EDIM;
    for (int e = threadIdx.x; e < EDIM; e += blockDim.x)
        xr[e] = te[e] + pe[e];
}

// ---------------- layernorm (one block per row) ----------------
__global__ void ln_k(const float* __restrict__ x,
                     const float* __restrict__ g,
                     const float* __restrict__ b,
                     float* __restrict__ y, int N) {
    int r = blockIdx.x;
    const float* xr = x + (size_t)r * N;
    float s = 0.f, s2 = 0.f;
    for (int i = threadIdx.x; i < N; i += blockDim.x) {
        float v = xr[i];
        s += v;
        s2 = fmaf(v, v, s2);
    }
    __shared__ float sh0[8], sh1[8];
    for (int o = 16; o > 0; o >>= 1) {
        s  += __shfl_down_sync(0xffffffffu, s, o);
        s2 += __shfl_down_sync(0xffffffffu, s2, o);
    }
    int w = threadIdx.x >> 5, lane = threadIdx.x & 31;
    if (lane == 0) { sh0[w] = s; sh1[w] = s2; }
    __syncthreads();
    if (threadIdx.x == 0) {
        float ts = 0.f, ts2 = 0.f;
        for (int i = 0; i < 8; i++) { ts += sh0[i]; ts2 += sh1[i]; }
        float mu = ts / (float)N;
        float var = ts2 / (float)N - mu * mu;
        sh0[0] = mu;
        sh1[0] = rsqrtf(var + 1e-5f);
    }
    __syncthreads();
    float mu = sh0[0], rstd = sh1[0];
    float* yr = y + (size_t)r * N;
    for (int i = threadIdx.x; i < N; i += blockDim.x)
        yr[i] = (xr[i] - mu) * rstd * g[i] + b[i];
}

// ---------------- SGEMM: C = A[M,K] @ B[K,N] (+bias/+relu/+residual) ----------------
// mode 0: plain   1: +bias   2: relu(+bias)   3: +bias +residual
// Requires K%4==0 and N%4==0 (true for all calls here). Edges zero-padded.
__global__ void __launch_bounds__(256, 2)
sgemm_k(const float* __restrict__ A, const float* __restrict__ Bm,
        const float* __restrict__ bias, const float* __restrict__ res,
        float* __restrict__ C, int M, int N, int K, int mode) {
    const int BM = 128, BN = 128, BK = 8, TM = 8, TN = 8;
    __shared__ float As[BK][BM];
    __shared__ float Bs[BK][BN];

    int tid = threadIdx.x;
    int bm = blockIdx.y * BM, bn = blockIdx.x * BN;
    int ty = tid / 16, tx = tid % 16;

    // A loader: one float4 per thread per tile (transposed store)
    int ar = tid >> 1;                  // 0..127
    int ac = (tid & 1) * 4;             // 0 or 4
    // B loader: one float4 per thread per tile
    int br = tid >> 5;                  // 0..7
    int bc = (tid & 31) * 4;            // 0..124

    float acc[TM][TN];
#pragma unroll
    for (int i = 0; i < TM; i++)
#pragma unroll
        for (int j = 0; j < TN; j++) acc[i][j] = 0.f;

    for (int k0 = 0; k0 < K; k0 += BK) {
        // load A tile (zero pad)
        {
            int grow = bm + ar, gcol = k0 + ac;
            float4 v = make_float4(0.f, 0.f, 0.f, 0.f);
            if (grow < M && gcol < K)
                v = *(const float4*)(A + (size_t)grow * K + gcol);
            As[ac + 0][ar] = v.x;
            As[ac + 1][ar] = v.y;
            As[ac + 2][ar] = v.z;
            As[ac + 3][ar] = v.w;
        }
        // load B tile (zero pad)
        {
            int grow = k0 + br, gcol = bn + bc;
            float4 v = make_float4(0.f, 0.f, 0.f, 0.f);
            if (grow < K && gcol < N)
                v = *(const float4*)(Bm + (size_t)grow * N + gcol);
            *(float4*)&Bs[br][bc] = v;
        }
        __syncthreads();

#pragma unroll
        for (int kk = 0; kk < BK; kk++) {
            float a[TM], b[TN];
            float4 a0 = *(const float4*)&As[kk][ty * TM];
            float4 a1 = *(const float4*)&As[kk][ty * TM + 4];
            a[0]=a0.x; a[1]=a0.y; a[2]=a0.z; a[3]=a0.w;
            a[4]=a1.x; a[5]=a1.y; a[6]=a1.z; a[7]=a1.w;
            float4 b0 = *(const float4*)&Bs[kk][tx * TN];
            float4 b1 = *(const float4*)&Bs[kk][tx * TN + 4];
            b[0]=b0.x; b[1]=b0.y; b[2]=b0.z; b[3]=b0.w;
            b[4]=b1.x; b[5]=b1.y; b[6]=b1.z; b[7]=b1.w;
#pragma unroll
            for (int i = 0; i < TM; i++)
#pragma unroll
                for (int j = 0; j < TN; j++)
                    acc[i][j] = fmaf(a[i], b[j], acc[i][j]);
        }
        __syncthreads();
    }

    // epilogue
#pragma unroll
    for (int i = 0; i < TM; i++) {
        int row = bm + ty * TM + i;
        if (row >= M) continue;
#pragma unroll
        for (int j = 0; j < TN; j++) {
            int col = bn + tx * TN + j;
            if (col >= N) continue;
            float v = acc[i][j];
            if (mode >= 1) v += bias[col];
            if (mode == 2) v = fmaxf(v, 0.f);
            if (mode == 3) v += res[(size_t)row * N + col];
            C[(size_t)row * N + col] = v;
        }
    }
}

// ---------------- attention: one block per (b,h), one thread per query ----------------
__global__ void __launch_bounds__(128)
attn_k(const float* __restrict__ q, const float* __restrict__ k,
       const float* __restrict__ v, float* __restrict__ att) {
    __shared__ float ks[TT][HS + 1];
    __shared__ float vs[TT][HS + 1];

    int bh = blockIdx.x;
    int b = bh / NH, h = bh % NH;
    int t = threadIdx.x;
    const size_t base = (size_t)b * TT * HH + (size_t)h * HS;

    for (int idx = t; idx < TT * HS; idx += 128) {
        int s = idx / HS, d = idx % HS;
        ks[s][d] = k[base + (size_t)s * HH + d];
        vs[s][d] = v[base + (size_t)s * HH + d];
    }
    __syncthreads();

    float qreg[HS];
#pragma unroll
    for (int d = 0; d < HS; d++)
        qreg[d] = q[base + (size_t)t * HH + d];

    float m = -1e30f, l = 0.f;
    float out[HS];
#pragma unroll
    for (int d = 0; d < HS; d++) out[d] = 0.f;

    for (int s = 0; s <= t; s++) {
        float dot = 0.f;
#pragma unroll
        for (int d = 0; d < HS; d++)
            dot = fmaf(qreg[d], ks[s][d], dot);
        float sc = dot * ATT_SCALE;
        float mn = fmaxf(m, sc);
        float corr = expf(m - mn);   // 0 on first iter (m=-1e30)
        float p = expf(sc - mn);
        l = l * corr + p;
#pragma unroll
        for (int d = 0; d < HS; d++)
            out[d] = out[d] * corr + p * vs[s][d];
        m = mn;
    }
    float inv = 1.f / l;
#pragma unroll
    for (int d = 0; d < HS; d++)
        att[base + (size_t)t * HH + d] = out[d] * inv;
}

// ---------------- launcher ----------------
static inline dim3 ggrid(int N) { return dim3((N + 127) / 128, (MM + 127) / 128); }

extern "C" void kernel_launch(void* const* d_in, const int* in_sizes, int n_in,
                              void* d_out, int out_size) {
    (void)in_sizes; (void)n_in;
    const int*   index = (const int*)  d_in[0];
    const float* tok   = (const float*)d_in[1];
    const float* pos   = (const float*)d_in[2];
    const float* wq    = (const float*)d_in[3];
    const float* wk    = (const float*)d_in[4];
    const float* wv    = (const float*)d_in[5];
    const float* wo    = (const float*)d_in[6];
    const float* bo    = (const float*)d_in[7];
    const float* ln1g  = (const float*)d_in[8];
    const float* ln1b  = (const float*)d_in[9];
    const float* ln2g  = (const float*)d_in[10];
    const float* ln2b  = (const float*)d_in[11];
    const float* w1    = (const float*)d_in[12];
    const float* b1    = (const float*)d_in[13];
    const float* w2    = (const float*)d_in[14];
    const float* b2    = (const float*)d_in[15];
    const float* lnfg  = (const float*)d_in[16];
    const float* lnfb  = (const float*)d_in[17];
    const float* wh    = (const float*)d_in[18];
    const float* bh    = (const float*)d_in[19];
    float* out = (float*)d_out;
    (void)out_size;

    float *x, *y, *q, *k, *v, *att, *hb;
    cudaGetSymbolAddress((void**)&x,   g_x);
    cudaGetSymbolAddress((void**)&y,   g_y);
    cudaGetSymbolAddress((void**)&q,   g_q);
    cudaGetSymbolAddress((void**)&k,   g_k);
    cudaGetSymbolAddress((void**)&v,   g_v);
    cudaGetSymbolAddress((void**)&att, g_att);
    cudaGetSymbolAddress((void**)&hb,  g_h);

    detect_k<<<1, 256>>>(index);
    embed_k<<<MM, 256>>>(index, tok, pos, x);

    for (int l = 0; l < NL; l++) {
        const float* pwq = wq + (size_t)l * EDIM * HH;
        const float* pwk = wk + (size_t)l * EDIM * HH;
        const float* pwv = wv + (size_t)l * EDIM * HH;
        const float* pwo = wo + (size_t)l * HH * EDIM;
        const float* pbo = bo + (size_t)l * EDIM;
        const float* g1  = ln1g + (size_t)l * EDIM;
        const float* be1 = ln1b + (size_t)l * EDIM;
        const float* g2  = ln2g + (size_t)l * EDIM;
        const float* be2 = ln2b + (size_t)l * EDIM;
        const float* pw1 = w1 + (size_t)l * EDIM * FF;
        const float* pb1 = b1 + (size_t)l * FF;
        const float* pw2 = w2 + (size_t)l * FF * EDIM;
        const float* pb2 = b2 + (size_t)l * EDIM;

        ln_k<<<MM, 256>>>(x, g1, be1, y, EDIM);

        sgemm_k<<<ggrid(HH), 256>>>(y, pwq, nullptr, nullptr, q, MM, HH, EDIM, 0);
        sgemm_k<<<ggrid(HH), 256>>>(y, pwk, nullptr, nullptr, k, MM, HH, EDIM, 0);
        sgemm_k<<<ggrid(HH), 256>>>(y, pwv, nullptr, nullptr, v, MM, HH, EDIM, 0);

        attn_k<<<BB * NH, 128>>>(q, k, v, att);

        sgemm_k<<<ggrid(EDIM), 256>>>(att, pwo, pbo, x, x, MM, EDIM, HH, 3);

        ln_k<<<MM, 256>>>(x, g2, be2, y, EDIM);

        sgemm_k<<<ggrid(FF), 256>>>(y, pw1, pb1, nullptr, hb, MM, FF, EDIM, 2);
        sgemm_k<<<ggrid(EDIM), 256>>>(hb, pw2, pb2, x, x, MM, EDIM, FF, 3);
    }

    ln_k<<<MM, 256>>>(x, lnfg, lnfb, y, EDIM);
    sgemm_k<<<ggrid(VOC), 256>>>(y, wh, bh, nullptr, out, MM, VOC, EDIM, 1);
}

// round 3
// speedup vs baseline: 4.0860x; 4.0860x over previous
#include <cuda_runtime.h>
#include <cstdint>
#include <math.h>

// ---------------- problem constants ----------------
#define EDIM 1140
#define HH   1120
#define NH   32
#define HS   35
#define NL   36
#define VOC  45000
#define TT   128
#define BB   8
#define MM   (BB*TT)       // 1024
#define FF   (4*EDIM)      // 4560
#define QKVN (3*HH)        // 3360
#define ATT_SCALE 0.16903085094570331f

// ---------------- scratch (device globals) ----------------
__device__ float g_x[MM * EDIM];
__device__ float g_y[MM * EDIM];
__device__ float g_qkv[MM * QKVN];
__device__ float g_att[MM * HH];
__device__ float g_h[MM * FF];
__device__ int   g_is64;

// ---------------- helpers ----------------
__device__ __forceinline__ uint32_t smem_u32(const void* p) {
    uint32_t a;
    asm("{ .reg .u64 t; cvta.to.shared.u64 t, %1; cvt.u32.u64 %0, t; }" : "=r"(a) : "l"(p));
    return a;
}
__device__ __forceinline__ float tf32rn(float x) {
    uint32_t u; asm("cvt.rn.tf32.f32 %0, %1;" : "=r"(u) : "f"(x));
    return __uint_as_float(u);
}
__device__ __forceinline__ uint32_t tf32rn_u(float x) {
    uint32_t u; asm("cvt.rn.tf32.f32 %0, %1;" : "=r"(u) : "f"(x));
    return u;
}
__device__ __forceinline__ void cpa16(uint32_t s, const void* g) {
    asm volatile("cp.async.cg.shared.global [%0], [%1], 16;" :: "r"(s), "l"(g) : "memory");
}
__device__ __forceinline__ void zfill16(uint32_t s) {
    asm volatile("st.shared.v4.b32 [%0], {%1,%1,%1,%1};" :: "r"(s), "r"(0) : "memory");
}
__device__ __forceinline__ void mma_tf32(float* d, const uint32_t* a, const uint32_t* b) {
    asm volatile(
        "mma.sync.aligned.m16n8k8.row.col.f32.tf32.tf32.f32 "
        "{%0,%1,%2,%3}, {%4,%5,%6,%7}, {%8,%9}, {%0,%1,%2,%3};"
        : "+f"(d[0]), "+f"(d[1]), "+f"(d[2]), "+f"(d[3])
        : "r"(a[0]), "r"(a[1]), "r"(a[2]), "r"(a[3]), "r"(b[0]), "r"(b[1]));
}

// ---------------- index dtype detection ----------------
__global__ void detect_k(const int* __restrict__ raw) {
    __shared__ int any;
    if (threadIdx.x == 0) any = 0;
    __syncthreads();
    int local = 0;
    for (int i = threadIdx.x; i < 512; i += blockDim.x)
        if (raw[2 * i + 1] != 0) local = 1;
    if (local) atomicOr(&any, 1);
    __syncthreads();
    if (threadIdx.x == 0) g_is64 = any ? 0 : 1;
}

// ---------------- embedding ----------------
__global__ void embed_k(const int* __restrict__ raw,
                        const float* __restrict__ tok,
                        const float* __restrict__ pos,
                        float* __restrict__ x) {
    int r = blockIdx.x;
    int t = r % TT;
    int idx = g_is64 ? raw[2 * r] : raw[r];
    const float* te = tok + (size_t)idx * EDIM;
    const float* pe = pos + (size_t)t * EDIM;
    float* xr = x + (size_t)r * EDIM;
    for (int e = threadIdx.x; e < EDIM; e += blockDim.x)
        xr[e] = te[e] + pe[e];
}

// ---------------- layernorm (output tf32-rounded: feeds MMA A operand) ----------------
__global__ void ln_k(const float* __restrict__ x,
                     const float* __restrict__ g,
                     const float* __restrict__ b,
                     float* __restrict__ y, int N) {
    int r = blockIdx.x;
    const float* xr = x + (size_t)r * N;
    float s = 0.f, s2 = 0.f;
    for (int i = threadIdx.x; i < N; i += blockDim.x) {
        float v = xr[i];
        s += v;
        s2 = fmaf(v, v, s2);
    }
    __shared__ float sh0[8], sh1[8];
    for (int o = 16; o > 0; o >>= 1) {
        s  += __shfl_down_sync(0xffffffffu, s, o);
        s2 += __shfl_down_sync(0xffffffffu, s2, o);
    }
    int w = threadIdx.x >> 5, lane = threadIdx.x & 31;
    if (lane == 0) { sh0[w] = s; sh1[w] = s2; }
    __syncthreads();
    if (threadIdx.x == 0) {
        float ts = 0.f, ts2 = 0.f;
        for (int i = 0; i < 8; i++) { ts += sh0[i]; ts2 += sh1[i]; }
        float mu = ts / (float)N;
        float var = ts2 / (float)N - mu * mu;
        sh0[0] = mu;
        sh1[0] = rsqrtf(var + 1e-5f);
    }
    __syncthreads();
    float mu = sh0[0], rstd = sh1[0];
    float* yr = y + (size_t)r * N;
    for (int i = threadIdx.x; i < N; i += blockDim.x)
        yr[i] = tf32rn((xr[i] - mu) * rstd * g[i] + b[i]);
}

// ---------------- tensor-core GEMM via mma.sync tf32 ----------------
// C[1024, Nc] (row stride ldc) = A[1024, K] @ B[K, Nc]  (B row-major, no transpose)
// mode 0: plain  1: +bias  2: relu(+bias), tf32-rounded  3: +bias +residual
// A is pre-rounded to tf32 by producers; B rounded to tf32 in-register here.
#define BKK 32
#define AST 36                      // A smem row stride (floats), conflict-free
#define BST 136                     // B smem row stride (floats), conflict-free
#define A_F (128 * AST)             // 4608 floats
#define B_F (BKK * BST)             // 4352 floats
#define STAGE_F (A_F + B_F)         // 8960 floats
#define STAGES 3
#define DSMEM (STAGES * STAGE_F * 4)   // 107520 bytes

__device__ __forceinline__ void load_slab(const float* __restrict__ A,
                                          const float* __restrict__ B,
                                          int Nc, int K, int bm, int bn, int k0,
                                          uint32_t sA, uint32_t sB, int tid) {
#pragma unroll
    for (int i = 0; i < 4; i++) {
        int c = tid + i * 256;          // 0..1023
        int row = c >> 3;               // 0..127
        int c4  = c & 7;                // 0..7
        int gk = k0 + c4 * 4;
        uint32_t off = sA + (uint32_t)(row * AST + c4 * 4) * 4;
        if (gk < K) cpa16(off, A + (size_t)(bm + row) * K + gk);
        else        zfill16(off);
    }
#pragma unroll
    for (int i = 0; i < 4; i++) {
        int c = tid + i * 256;
        int row = c >> 5;               // 0..31 (k)
        int c4  = c & 31;               // 0..31
        int gk = k0 + row;
        int col = bn + c4 * 4;
        uint32_t off = sB + (uint32_t)(row * BST + c4 * 4) * 4;
        if (gk < K && col < Nc) cpa16(off, B + (size_t)gk * Nc + col);
        else                    zfill16(off);
    }
}

__global__ void __launch_bounds__(256, 2)
tgemm_k(const float* __restrict__ A, const float* __restrict__ B,
        const float* __restrict__ bias, const float* __restrict__ res,
        float* __restrict__ C, int Nc, int K, int ldc, int mode) {
    extern __shared__ float smf[];
    int tid = threadIdx.x;
    int bn = blockIdx.x * 128, bm = blockIdx.y * 128;
    int warp = tid >> 5, lane = tid & 31;
    int wm = warp >> 2, wn = warp & 3;      // 2 x 4 warp grid
    int g = lane >> 2, tig = lane & 3;

    uint32_t sbase = smem_u32(smf);

    float acc[4][4][4];
#pragma unroll
    for (int mt = 0; mt < 4; mt++)
#pragma unroll
        for (int nt = 0; nt < 4; nt++)
#pragma unroll
            for (int j = 0; j < 4; j++) acc[mt][nt][j] = 0.f;

    const int NS = (K + BKK - 1) / BKK;

    // prologue: stages 0, 1
    load_slab(A, B, Nc, K, bm, bn, 0,
              sbase, sbase + A_F * 4, tid);
    asm volatile("cp.async.commit_group;" ::: "memory");
    load_slab(A, B, Nc, K, bm, bn, BKK,
              sbase + STAGE_F * 4, sbase + (STAGE_F + A_F) * 4, tid);
    asm volatile("cp.async.commit_group;" ::: "memory");

    for (int ksl = 0; ksl < NS; ksl++) {
        int st = ksl - (ksl / STAGES) * STAGES;
        const float* As = smf + st * STAGE_F;
        const float* Bs = As + A_F;

        asm volatile("cp.async.wait_group 1;" ::: "memory");
        __syncthreads();

        // prefetch stage ksl+2 (overwrites stage consumed at ksl-1; safe after barrier)
        int nk = ksl + 2;
        if (nk < NS) {
            int pst = nk - (nk / STAGES) * STAGES;
            load_slab(A, B, Nc, K, bm, bn, nk * BKK,
                      sbase + (uint32_t)(pst * STAGE_F) * 4,
                      sbase + (uint32_t)(pst * STAGE_F + A_F) * 4, tid);
        }
        asm volatile("cp.async.commit_group;" ::: "memory");

        // compute this slab: 4 k-slices of 8
#pragma unroll
        for (int ks = 0; ks < 4; ks++) {
            int k0 = ks * 8;
            uint32_t a[4][4];
#pragma unroll
            for (int mt = 0; mt < 4; mt++) {
                const float* ap = As + (wm * 64 + mt * 16 + g) * AST + k0 + tig;
                a[mt][0] = __float_as_uint(ap[0]);
                a[mt][1] = __float_as_uint(ap[8 * AST]);
                a[mt][2] = __float_as_uint(ap[4]);
                a[mt][3] = __float_as_uint(ap[8 * AST + 4]);
            }
            uint32_t b[4][2];
#pragma unroll
            for (int nt = 0; nt < 4; nt++) {
                const float* bp = Bs + (k0 + tig) * BST + wn * 32 + nt * 8 + g;
                b[nt][0] = tf32rn_u(bp[0]);
                b[nt][1] = tf32rn_u(bp[4 * BST]);
            }
#pragma unroll
            for (int mt = 0; mt < 4; mt++)
#pragma unroll
                for (int nt = 0; nt < 4; nt++)
                    mma_tf32(acc[mt][nt], a[mt], b[nt]);
        }
    }

    // epilogue
    bool fullN = (bn + 128) <= Nc;
#pragma unroll
    for (int mt = 0; mt < 4; mt++) {
        int r0 = bm + wm * 64 + mt * 16 + g;
        int r1 = r0 + 8;
#pragma unroll
        for (int nt = 0; nt < 4; nt++) {
            int col = bn + wn * 32 + nt * 8 + 2 * tig;
            float v0 = acc[mt][nt][0], v1 = acc[mt][nt][1];
            float v2 = acc[mt][nt][2], v3 = acc[mt][nt][3];
            if (fullN) {
                if (mode >= 1) {
                    float2 bb = *(const float2*)(bias + col);
                    v0 += bb.x; v1 += bb.y; v2 += bb.x; v3 += bb.y;
                }
                if (mode == 2) {
                    v0 = tf32rn(fmaxf(v0, 0.f)); v1 = tf32rn(fmaxf(v1, 0.f));
                    v2 = tf32rn(fmaxf(v2, 0.f)); v3 = tf32rn(fmaxf(v3, 0.f));
                }
                if (mode == 3) {
                    float2 q0 = *(const float2*)(res + (size_t)r0 * ldc + col);
                    float2 q1 = *(const float2*)(res + (size_t)r1 * ldc + col);
                    v0 += q0.x; v1 += q0.y; v2 += q1.x; v3 += q1.y;
                }
                *(float2*)(C + (size_t)r0 * ldc + col) = make_float2(v0, v1);
                *(float2*)(C + (size_t)r1 * ldc + col) = make_float2(v2, v3);
            } else {
                float vv[4] = {v0, v1, v2, v3};
                int rr[4] = {r0, r0, r1, r1};
                int cc[4] = {col, col + 1, col, col + 1};
#pragma unroll
                for (int j = 0; j < 4; j++) {
                    if (cc[j] >= Nc) continue;
                    float v = vv[j];
                    if (mode >= 1) v += bias[cc[j]];
                    if (mode == 2) v = tf32rn(fmaxf(v, 0.f));
                    if (mode == 3) v += res[(size_t)rr[j] * ldc + cc[j]];
                    C[(size_t)rr[j] * ldc + cc[j]] = v;
                }
            }
        }
    }
}

// ---------------- attention (q,k,v packed in one [MM, 3360] buffer) ----------------
__global__ void __launch_bounds__(128)
attn_k(const float* __restrict__ qkv, float* __restrict__ att) {
    __shared__ float ks[TT][HS + 1];
    __shared__ float vs[TT][HS + 1];

    int bh = blockIdx.x;
    int b = bh / NH, h = bh % NH;
    int t = threadIdx.x;
    const size_t rbase = (size_t)b * TT * QKVN;
    const int hoff = h * HS;

    for (int idx = t; idx < TT * HS; idx += 128) {
        int s = idx / HS, d = idx % HS;
        ks[s][d] = qkv[rbase + (size_t)s * QKVN + HH + hoff + d];
        vs[s][d] = qkv[rbase + (size_t)s * QKVN + 2 * HH + hoff + d];
    }
    __syncthreads();

    float qreg[HS];
#pragma unroll
    for (int d = 0; d < HS; d++)
        qreg[d] = qkv[rbase + (size_t)t * QKVN + hoff + d];

    float m = -1e30f, l = 0.f;
    float out[HS];
#pragma unroll
    for (int d = 0; d < HS; d++) out[d] = 0.f;

    for (int s = 0; s <= t; s++) {
        float dot = 0.f;
#pragma unroll
        for (int d = 0; d < HS; d++)
            dot = fmaf(qreg[d], ks[s][d], dot);
        float sc = dot * ATT_SCALE;
        float mn = fmaxf(m, sc);
        float corr = expf(m - mn);
        float p = expf(sc - mn);
        l = l * corr + p;
#pragma unroll
        for (int d = 0; d < HS; d++)
            out[d] = out[d] * corr + p * vs[s][d];
        m = mn;
    }
    float inv = 1.f / l;
    size_t obase = (size_t)(b * TT + t) * HH + hoff;
#pragma unroll
    for (int d = 0; d < HS; d++)
        att[obase + d] = tf32rn(out[d] * inv);
}

// ---------------- launcher ----------------
static inline dim3 tgrid(int N) { return dim3((N + 127) / 128, MM / 128); }

extern "C" void kernel_launch(void* const* d_in, const int* in_sizes, int n_in,
                              void* d_out, int out_size) {
    (void)in_sizes; (void)n_in; (void)out_size;
    const int*   index = (const int*)  d_in[0];
    const float* tok   = (const float*)d_in[1];
    const float* pos   = (const float*)d_in[2];
    const float* wq    = (const float*)d_in[3];
    const float* wk    = (const float*)d_in[4];
    const float* wv    = (const float*)d_in[5];
    const float* wo    = (const float*)d_in[6];
    const float* bo    = (const float*)d_in[7];
    const float* ln1g  = (const float*)d_in[8];
    const float* ln1b  = (const float*)d_in[9];
    const float* ln2g  = (const float*)d_in[10];
    const float* ln2b  = (const float*)d_in[11];
    const float* w1    = (const float*)d_in[12];
    const float* b1    = (const float*)d_in[13];
    const float* w2    = (const float*)d_in[14];
    const float* b2    = (const float*)d_in[15];
    const float* lnfg  = (const float*)d_in[16];
    const float* lnfb  = (const float*)d_in[17];
    const float* wh    = (const float*)d_in[18];
    const float* bh    = (const float*)d_in[19];
    float* out = (float*)d_out;

    float *x, *y, *qkv, *att, *hb;
    cudaGetSymbolAddress((void**)&x,   g_x);
    cudaGetSymbolAddress((void**)&y,   g_y);
    cudaGetSymbolAddress((void**)&qkv, g_qkv);
    cudaGetSymbolAddress((void**)&att, g_att);
    cudaGetSymbolAddress((void**)&hb,  g_h);

    cudaFuncSetAttribute(tgemm_k, cudaFuncAttributeMaxDynamicSharedMemorySize, DSMEM);

    detect_k<<<1, 256>>>(index);
    embed_k<<<MM, 256>>>(index, tok, pos, x);

    for (int l = 0; l < NL; l++) {
        const float* pwq = wq + (size_t)l * EDIM * HH;
        const float* pwk = wk + (size_t)l * EDIM * HH;
        const float* pwv = wv + (size_t)l * EDIM * HH;
        const float* pwo = wo + (size_t)l * HH * EDIM;
        const float* pbo = bo + (size_t)l * EDIM;
        const float* g1  = ln1g + (size_t)l * EDIM;
        const float* be1 = ln1b + (size_t)l * EDIM;
        const float* g2  = ln2g + (size_t)l * EDIM;
        const float* be2 = ln2b + (size_t)l * EDIM;
        const float* pw1 = w1 + (size_t)l * EDIM * FF;
        const float* pb1 = b1 + (size_t)l * FF;
        const float* pw2 = w2 + (size_t)l * FF * EDIM;
        const float* pb2 = b2 + (size_t)l * EDIM;

        ln_k<<<MM, 256>>>(x, g1, be1, y, EDIM);

        // QKV: three GEMMs writing strided into the packed [MM, 3360] buffer
        tgemm_k<<<tgrid(HH), 256, DSMEM>>>(y, pwq, nullptr, nullptr, qkv,            HH, EDIM, QKVN, 0);
        tgemm_k<<<tgrid(HH), 256, DSMEM>>>(y, pwk, nullptr, nullptr, qkv + HH,       HH, EDIM, QKVN, 0);
        tgemm_k<<<tgrid(HH), 256, DSMEM>>>(y, pwv, nullptr, nullptr, qkv + 2 * HH,   HH, EDIM, QKVN, 0);

        attn_k<<<BB * NH, 128>>>(qkv, att);

        tgemm_k<<<tgrid(EDIM), 256, DSMEM>>>(att, pwo, pbo, x, x, EDIM, HH, EDIM, 3);

        ln_k<<<MM, 256>>>(x, g2, be2, y, EDIM);

        tgemm_k<<<tgrid(FF), 256, DSMEM>>>(y, pw1, pb1, nullptr, hb, FF, EDIM, FF, 2);
        tgemm_k<<<tgrid(EDIM), 256, DSMEM>>>(hb, pw2, pb2, x, x, EDIM, FF, EDIM, 3);
    }

    ln_k<<<MM, 256>>>(x, lnfg, lnfb, y, EDIM);
    tgemm_k<<<tgrid(VOC), 256, DSMEM>>>(y, wh, bh, nullptr, out, VOC, EDIM, VOC, 1);
}

// round 4
// speedup vs baseline: 5.0545x; 1.2370x over previous
#include <cuda_runtime.h>
#include <cstdint>
#include <math.h>

// ---------------- problem constants ----------------
#define EDIM 1140
#define HH   1120
#define NH   32
#define HS   35
#define NL   36
#define VOC  45000
#define TT   128
#define BB   8
#define MM   (BB*TT)       // 1024
#define FF   (4*EDIM)      // 4560
#define QKVN (3*HH)        // 3360
#define ATT_SCALE 0.16903085094570331f

// ---------------- scratch (device globals) ----------------
__device__ float g_x[MM * EDIM];
__device__ float g_y[MM * EDIM];
__device__ float g_qkv[MM * QKVN];
__device__ float g_att[MM * HH];
__device__ float g_h[MM * FF];
__device__ int   g_is64;

// ---------------- helpers ----------------
__device__ __forceinline__ uint32_t smem_u32(const void* p) {
    uint32_t a;
    asm("{ .reg .u64 t; cvta.to.shared.u64 t, %1; cvt.u32.u64 %0, t; }" : "=r"(a) : "l"(p));
    return a;
}
__device__ __forceinline__ float tf32rn(float x) {
    uint32_t u; asm("cvt.rn.tf32.f32 %0, %1;" : "=r"(u) : "f"(x));
    return __uint_as_float(u);
}
__device__ __forceinline__ uint32_t tf32rn_u(float x) {
    uint32_t u; asm("cvt.rn.tf32.f32 %0, %1;" : "=r"(u) : "f"(x));
    return u;
}
__device__ __forceinline__ void cpa16(uint32_t s, const void* g) {
    asm volatile("cp.async.cg.shared.global [%0], [%1], 16;" :: "r"(s), "l"(g) : "memory");
}
__device__ __forceinline__ void zfill16(uint32_t s) {
    asm volatile("st.shared.v4.b32 [%0], {%1,%1,%1,%1};" :: "r"(s), "r"(0) : "memory");
}
__device__ __forceinline__ void mma_tf32(float* d, const uint32_t* a, const uint32_t* b) {
    asm volatile(
        "mma.sync.aligned.m16n8k8.row.col.f32.tf32.tf32.f32 "
        "{%0,%1,%2,%3}, {%4,%5,%6,%7}, {%8,%9}, {%0,%1,%2,%3};"
        : "+f"(d[0]), "+f"(d[1]), "+f"(d[2]), "+f"(d[3])
        : "r"(a[0]), "r"(a[1]), "r"(a[2]), "r"(a[3]), "r"(b[0]), "r"(b[1]));
}

// ---------------- index dtype detection ----------------
__global__ void detect_k(const int* __restrict__ raw) {
    __shared__ int any;
    if (threadIdx.x == 0) any = 0;
    __syncthreads();
    int local = 0;
    for (int i = threadIdx.x; i < 512; i += blockDim.x)
        if (raw[2 * i + 1] != 0) local = 1;
    if (local) atomicOr(&any, 1);
    __syncthreads();
    if (threadIdx.x == 0) g_is64 = any ? 0 : 1;
}

// ---------------- embedding ----------------
__global__ void embed_k(const int* __restrict__ raw,
                        const float* __restrict__ tok,
                        const float* __restrict__ pos,
                        float* __restrict__ x) {
    int r = blockIdx.x;
    int t = r % TT;
    int idx = g_is64 ? raw[2 * r] : raw[r];
    const float* te = tok + (size_t)idx * EDIM;
    const float* pe = pos + (size_t)t * EDIM;
    float* xr = x + (size_t)r * EDIM;
    for (int e = threadIdx.x; e < EDIM; e += blockDim.x)
        xr[e] = te[e] + pe[e];
}

// ---------------- layernorm (output tf32-rounded: feeds MMA A operand) ----------------
__global__ void ln_k(const float* __restrict__ x,
                     const float* __restrict__ g,
                     const float* __restrict__ b,
                     float* __restrict__ y, int N) {
    int r = blockIdx.x;
    const float* xr = x + (size_t)r * N;
    float s = 0.f, s2 = 0.f;
    for (int i = threadIdx.x; i < N; i += blockDim.x) {
        float v = xr[i];
        s += v;
        s2 = fmaf(v, v, s2);
    }
    __shared__ float sh0[8], sh1[8];
    for (int o = 16; o > 0; o >>= 1) {
        s  += __shfl_down_sync(0xffffffffu, s, o);
        s2 += __shfl_down_sync(0xffffffffu, s2, o);
    }
    int w = threadIdx.x >> 5, lane = threadIdx.x & 31;
    if (lane == 0) { sh0[w] = s; sh1[w] = s2; }
    __syncthreads();
    if (threadIdx.x == 0) {
        float ts = 0.f, ts2 = 0.f;
        for (int i = 0; i < 8; i++) { ts += sh0[i]; ts2 += sh1[i]; }
        float mu = ts / (float)N;
        float var = ts2 / (float)N - mu * mu;
        sh0[0] = mu;
        sh1[0] = rsqrtf(var + 1e-5f);
    }
    __syncthreads();
    float mu = sh0[0], rstd = sh1[0];
    float* yr = y + (size_t)r * N;
    for (int i = threadIdx.x; i < N; i += blockDim.x)
        yr[i] = tf32rn((xr[i] - mu) * rstd * g[i] + b[i]);
}

// ---------------- tensor-core GEMM via mma.sync tf32 ----------------
// C[1024, *] = A[1024, K] @ B[K, Nc]  (B row-major, K-major direct; no transpose)
// Templated on BM (CTA row-tile): 128 -> 2x4 warps (64x32 each); 64 -> 1x8 warps (64x16)
// gridDim.z selects B0/B1/B2 with output column offset z*zoff (fused QKV).
// mode 0: plain  1: +bias  2: relu(+bias), tf32-rounded  3: +bias +residual
#define BKK 32
#define AST 36                      // A smem row stride (floats), conflict-free
#define BST 136                     // B smem row stride (floats), conflict-free
#define B_F (BKK * BST)             // 4352 floats

template<int BM>
__device__ __forceinline__ void load_slab(const float* __restrict__ A,
                                          const float* __restrict__ B,
                                          int Nc, int K, int bm, int bn, int k0,
                                          uint32_t sA, uint32_t sB, int tid) {
    // A: BM rows x 32 cols -> BM*8 float4
#pragma unroll
    for (int i = 0; i < BM / 32; i++) {
        int c = tid + i * 256;
        int row = c >> 3;
        int c4  = c & 7;
        int gk = k0 + c4 * 4;
        uint32_t off = sA + (uint32_t)(row * AST + c4 * 4) * 4;
        if (gk < K) cpa16(off, A + (size_t)(bm + row) * K + gk);
        else        zfill16(off);
    }
    // B: 32 rows x 128 cols -> 1024 float4
#pragma unroll
    for (int i = 0; i < 4; i++) {
        int c = tid + i * 256;
        int row = c >> 5;
        int c4  = c & 31;
        int gk = k0 + row;
        int col = bn + c4 * 4;
        uint32_t off = sB + (uint32_t)(row * BST + c4 * 4) * 4;
        if (gk < K && col < Nc) cpa16(off, B + (size_t)gk * Nc + col);
        else                    zfill16(off);
    }
}

template<int BM>
__global__ void __launch_bounds__(256, 2)
tgemm_k(const float* __restrict__ A,
        const float* __restrict__ B0, const float* __restrict__ B1,
        const float* __restrict__ B2,
        const float* __restrict__ bias, const float* __restrict__ res,
        float* __restrict__ C, int Nc, int K, int ldc, int zoff, int mode) {
    constexpr int NT = (BM == 128) ? 4 : 2;       // n-subtiles per warp
    constexpr int A_F = BM * AST;
    constexpr int STAGE_F = A_F + B_F;

    extern __shared__ float smf[];
    const float* Bm = (blockIdx.z == 0) ? B0 : ((blockIdx.z == 1) ? B1 : B2);
    const int coff = blockIdx.z * zoff;

    int tid = threadIdx.x;
    int bn = blockIdx.x * 128, bm = blockIdx.y * BM;
    int warp = tid >> 5, lane = tid & 31;
    int wm = (BM == 128) ? (warp >> 2) : 0;
    int wn = (BM == 128) ? (warp & 3) : warp;
    int g = lane >> 2, tig = lane & 3;

    uint32_t sbase = smem_u32(smf);

    float acc[4][NT][4];
#pragma unroll
    for (int mt = 0; mt < 4; mt++)
#pragma unroll
        for (int nt = 0; nt < NT; nt++)
#pragma unroll
            for (int j = 0; j < 4; j++) acc[mt][nt][j] = 0.f;

    const int NS = (K + BKK - 1) / BKK;

    // prologue: stage 0
    load_slab<BM>(A, Bm, Nc, K, bm, bn, 0, sbase, sbase + A_F * 4, tid);
    asm volatile("cp.async.commit_group;" ::: "memory");

    for (int ksl = 0; ksl < NS; ksl++) {
        int st = ksl & 1;
        const float* As = smf + st * STAGE_F;
        const float* Bs = As + A_F;

        // issue next stage's loads (buffer was consumed at ksl-1; fenced by the
        // trailing __syncthreads of the previous iteration)
        int nk = ksl + 1;
        if (nk < NS) {
            int pst = nk & 1;
            load_slab<BM>(A, Bm, Nc, K, bm, bn, nk * BKK,
                          sbase + (uint32_t)(pst * STAGE_F) * 4,
                          sbase + (uint32_t)(pst * STAGE_F + A_F) * 4, tid);
        }
        asm volatile("cp.async.commit_group;" ::: "memory");

        // wait for stage ksl (second-newest group)
        asm volatile("cp.async.wait_group 1;" ::: "memory");
        __syncthreads();

        // compute this slab: 4 k-slices of 8
#pragma unroll
        for (int ks = 0; ks < 4; ks++) {
            int k0 = ks * 8;
            uint32_t a[4][4];
#pragma unroll
            for (int mt = 0; mt < 4; mt++) {
                const float* ap = As + (wm * 64 + mt * 16 + g) * AST + k0 + tig;
                a[mt][0] = __float_as_uint(ap[0]);
                a[mt][1] = __float_as_uint(ap[8 * AST]);
                a[mt][2] = __float_as_uint(ap[4]);
                a[mt][3] = __float_as_uint(ap[8 * AST + 4]);
            }
            uint32_t b[NT][2];
#pragma unroll
            for (int nt = 0; nt < NT; nt++) {
                const float* bp = Bs + (k0 + tig) * BST + wn * (NT * 8) + nt * 8 + g;
                b[nt][0] = tf32rn_u(bp[0]);
                b[nt][1] = tf32rn_u(bp[4 * BST]);
            }
#pragma unroll
            for (int mt = 0; mt < 4; mt++)
#pragma unroll
                for (int nt = 0; nt < NT; nt++)
                    mma_tf32(acc[mt][nt], a[mt], b[nt]);
        }
        __syncthreads();   // all warps done with this buffer before it is reloaded
    }

    // epilogue
    bool fullN = (bn + 128) <= Nc;
#pragma unroll
    for (int mt = 0; mt < 4; mt++) {
        int r0 = bm + wm * 64 + mt * 16 + g;
        int r1 = r0 + 8;
#pragma unroll
        for (int nt = 0; nt < NT; nt++) {
            int lcol = bn + wn * (NT * 8) + nt * 8 + 2 * tig;
            int col = coff + lcol;
            float v0 = acc[mt][nt][0], v1 = acc[mt][nt][1];
            float v2 = acc[mt][nt][2], v3 = acc[mt][nt][3];
            if (fullN) {
                if (mode >= 1) {
                    float2 bb = *(const float2*)(bias + lcol);
                    v0 += bb.x; v1 += bb.y; v2 += bb.x; v3 += bb.y;
                }
                if (mode == 2) {
                    v0 = tf32rn(fmaxf(v0, 0.f)); v1 = tf32rn(fmaxf(v1, 0.f));
                    v2 = tf32rn(fmaxf(v2, 0.f)); v3 = tf32rn(fmaxf(v3, 0.f));
                }
                if (mode == 3) {
                    float2 q0 = *(const float2*)(res + (size_t)r0 * ldc + col);
                    float2 q1 = *(const float2*)(res + (size_t)r1 * ldc + col);
                    v0 += q0.x; v1 += q0.y; v2 += q1.x; v3 += q1.y;
                }
                *(float2*)(C + (size_t)r0 * ldc + col) = make_float2(v0, v1);
                *(float2*)(C + (size_t)r1 * ldc + col) = make_float2(v2, v3);
            } else {
                float vv[4] = {v0, v1, v2, v3};
                int rr[4] = {r0, r0, r1, r1};
                int cc[4] = {lcol, lcol + 1, lcol, lcol + 1};
#pragma unroll
                for (int j = 0; j < 4; j++) {
                    if (cc[j] >= Nc) continue;
                    float v = vv[j];
                    if (mode >= 1) v += bias[cc[j]];
                    if (mode == 2) v = tf32rn(fmaxf(v, 0.f));
                    if (mode == 3) v += res[(size_t)rr[j] * ldc + coff + cc[j]];
                    C[(size_t)rr[j] * ldc + coff + cc[j]] = v;
                }
            }
        }
    }
}

#define DS128 (2 * (128 * AST + B_F) * 4)   // 71680 B
#define DS64  (2 * (64  * AST + B_F) * 4)   // 53248 B

// ---------------- attention (q,k,v packed in one [MM, 3360] buffer) ----------------
__global__ void __launch_bounds__(128)
attn_k(const float* __restrict__ qkv, float* __restrict__ att) {
    __shared__ float ks[TT][HS + 1];
    __shared__ float vs[TT][HS + 1];

    int bh = blockIdx.x;
    int b = bh / NH, h = bh % NH;
    int t = threadIdx.x;
    const size_t rbase = (size_t)b * TT * QKVN;
    const int hoff = h * HS;

    for (int idx = t; idx < TT * HS; idx += 128) {
        int s = idx / HS, d = idx % HS;
        ks[s][d] = qkv[rbase + (size_t)s * QKVN + HH + hoff + d];
        vs[s][d] = qkv[rbase + (size_t)s * QKVN + 2 * HH + hoff + d];
    }
    __syncthreads();

    float qreg[HS];
#pragma unroll
    for (int d = 0; d < HS; d++)
        qreg[d] = qkv[rbase + (size_t)t * QKVN + hoff + d];

    float m = -1e30f, l = 0.f;
    float out[HS];
#pragma unroll
    for (int d = 0; d < HS; d++) out[d] = 0.f;

    for (int s = 0; s <= t; s++) {
        float dot = 0.f;
#pragma unroll
        for (int d = 0; d < HS; d++)
            dot = fmaf(qreg[d], ks[s][d], dot);
        float sc = dot * ATT_SCALE;
        float mn = fmaxf(m, sc);
        float corr = expf(m - mn);
        float p = expf(sc - mn);
        l = l * corr + p;
#pragma unroll
        for (int d = 0; d < HS; d++)
            out[d] = out[d] * corr + p * vs[s][d];
        m = mn;
    }
    float inv = 1.f / l;
    size_t obase = (size_t)(b * TT + t) * HH + hoff;
#pragma unroll
    for (int d = 0; d < HS; d++)
        att[obase + d] = tf32rn(out[d] * inv);
}

// ---------------- launcher ----------------
extern "C" void kernel_launch(void* const* d_in, const int* in_sizes, int n_in,
                              void* d_out, int out_size) {
    (void)in_sizes; (void)n_in; (void)out_size;
    const int*   index = (const int*)  d_in[0];
    const float* tok   = (const float*)d_in[1];
    const float* pos   = (const float*)d_in[2];
    const float* wq    = (const float*)d_in[3];
    const float* wk    = (const float*)d_in[4];
    const float* wv    = (const float*)d_in[5];
    const float* wo    = (const float*)d_in[6];
    const float* bo    = (const float*)d_in[7];
    const float* ln1g  = (const float*)d_in[8];
    const float* ln1b  = (const float*)d_in[9];
    const float* ln2g  = (const float*)d_in[10];
    const float* ln2b  = (const float*)d_in[11];
    const float* w1    = (const float*)d_in[12];
    const float* b1    = (const float*)d_in[13];
    const float* w2    = (const float*)d_in[14];
    const float* b2    = (const float*)d_in[15];
    const float* lnfg  = (const float*)d_in[16];
    const float* lnfb  = (const float*)d_in[17];
    const float* wh    = (const float*)d_in[18];
    const float* bh    = (const float*)d_in[19];
    float* out = (float*)d_out;

    float *x, *y, *qkv, *att, *hb;
    cudaGetSymbolAddress((void**)&x,   g_x);
    cudaGetSymbolAddress((void**)&y,   g_y);
    cudaGetSymbolAddress((void**)&qkv, g_qkv);
    cudaGetSymbolAddress((void**)&att, g_att);
    cudaGetSymbolAddress((void**)&hb,  g_h);

    cudaFuncSetAttribute(tgemm_k<128>, cudaFuncAttributeMaxDynamicSharedMemorySize, DS128);
    cudaFuncSetAttribute(tgemm_k<64>,  cudaFuncAttributeMaxDynamicSharedMemorySize, DS64);

    detect_k<<<1, 256>>>(index);
    embed_k<<<MM, 256>>>(index, tok, pos, x);

    for (int l = 0; l < NL; l++) {
        const float* pwq = wq + (size_t)l * EDIM * HH;
        const float* pwk = wk + (size_t)l * EDIM * HH;
        const float* pwv = wv + (size_t)l * EDIM * HH;
        const float* pwo = wo + (size_t)l * HH * EDIM;
        const float* pbo = bo + (size_t)l * EDIM;
        const float* g1  = ln1g + (size_t)l * EDIM;
        const float* be1 = ln1b + (size_t)l * EDIM;
        const float* g2  = ln2g + (size_t)l * EDIM;
        const float* be2 = ln2b + (size_t)l * EDIM;
        const float* pw1 = w1 + (size_t)l * EDIM * FF;
        const float* pb1 = b1 + (size_t)l * FF;
        const float* pw2 = w2 + (size_t)l * FF * EDIM;
        const float* pb2 = b2 + (size_t)l * EDIM;

        ln_k<<<MM, 256>>>(x, g1, be1, y, EDIM);

        // fused QKV: z selects wq/wk/wv, output col offset z*HH into packed buffer
        tgemm_k<128><<<dim3(9, 8, 3), 256, DS128>>>(
            y, pwq, pwk, pwv, nullptr, nullptr, qkv, HH, EDIM, QKVN, HH, 0);

        attn_k<<<BB * NH, 128>>>(qkv, att);

        tgemm_k<64><<<dim3(9, 16, 1), 256, DS64>>>(
            att, pwo, pwo, pwo, pbo, x, x, EDIM, HH, EDIM, 0, 3);

        ln_k<<<MM, 256>>>(x, g2, be2, y, EDIM);

        tgemm_k<128><<<dim3(36, 8, 1), 256, DS128>>>(
            y, pw1, pw1, pw1, pb1, nullptr, hb, FF, EDIM, FF, 0, 2);

        tgemm_k<64><<<dim3(9, 16, 1), 256, DS64>>>(
            hb, pw2, pw2, pw2, pb2, x, x, EDIM, FF, EDIM, 0, 3);
    }

    ln_k<<<MM, 256>>>(x, lnfg, lnfb, y, EDIM);
    tgemm_k<128><<<dim3(352, 8, 1), 256, DS128>>>(
        y, wh, wh, wh, bh, nullptr, out, VOC, EDIM, VOC, 0, 1);
}

// round 5
// speedup vs baseline: 5.8089x; 1.1493x over previous
#include <cuda_runtime.h>
#include <cstdint>
#include <math.h>

// ---------------- problem constants ----------------
#define EDIM 1140
#define HH   1120
#define NH   32
#define HS   35
#define NL   36
#define VOC  45000
#define TT   128
#define BB   8
#define MM   (BB*TT)       // 1024
#define FF   (4*EDIM)      // 4560
#define QKVN (3*HH)        // 3360
#define ATT_SCALE 0.16903085094570331f

// ---------------- scratch (device globals) ----------------
__device__ float g_x[MM * EDIM];
__device__ float g_y[MM * EDIM];
__device__ float g_qkv[MM * QKVN];
__device__ float g_att[MM * HH];
__device__ float g_h[MM * FF];
__device__ float g_part[4 * MM * EDIM];   // split-K partials
__device__ int   g_is64;

// ---------------- helpers ----------------
__device__ __forceinline__ uint32_t smem_u32(const void* p) {
    uint32_t a;
    asm("{ .reg .u64 t; cvta.to.shared.u64 t, %1; cvt.u32.u64 %0, t; }" : "=r"(a) : "l"(p));
    return a;
}
__device__ __forceinline__ float tf32rn(float x) {
    uint32_t u; asm("cvt.rn.tf32.f32 %0, %1;" : "=r"(u) : "f"(x));
    return __uint_as_float(u);
}
__device__ __forceinline__ uint32_t tf32rn_u(float x) {
    uint32_t u; asm("cvt.rn.tf32.f32 %0, %1;" : "=r"(u) : "f"(x));
    return u;
}
__device__ __forceinline__ void cpa16(uint32_t s, const void* g) {
    asm volatile("cp.async.cg.shared.global [%0], [%1], 16;" :: "r"(s), "l"(g) : "memory");
}
__device__ __forceinline__ void zfill16(uint32_t s) {
    asm volatile("st.shared.v4.b32 [%0], {%1,%1,%1,%1};" :: "r"(s), "r"(0) : "memory");
}
__device__ __forceinline__ void mma_tf32(float* d, const uint32_t* a, const uint32_t* b) {
    asm volatile(
        "mma.sync.aligned.m16n8k8.row.col.f32.tf32.tf32.f32 "
        "{%0,%1,%2,%3}, {%4,%5,%6,%7}, {%8,%9}, {%0,%1,%2,%3};"
        : "+f"(d[0]), "+f"(d[1]), "+f"(d[2]), "+f"(d[3])
        : "r"(a[0]), "r"(a[1]), "r"(a[2]), "r"(a[3]), "r"(b[0]), "r"(b[1]));
}
// ldmatrix x4: loads the four 8x8(b16) quadrants = tf32 m16n8k8 A fragment
__device__ __forceinline__ void ldsm4(uint32_t* r, uint32_t a) {
    asm volatile("ldmatrix.sync.aligned.m8n8.x4.shared.b16 {%0,%1,%2,%3}, [%4];"
        : "=r"(r[0]), "=r"(r[1]), "=r"(r[2]), "=r"(r[3]) : "r"(a));
}

// ---------------- index dtype detection ----------------
__global__ void detect_k(const int* __restrict__ raw) {
    __shared__ int any;
    if (threadIdx.x == 0) any = 0;
    __syncthreads();
    int local = 0;
    for (int i = threadIdx.x; i < 512; i += blockDim.x)
        if (raw[2 * i + 1] != 0) local = 1;
    if (local) atomicOr(&any, 1);
    __syncthreads();
    if (threadIdx.x == 0) g_is64 = any ? 0 : 1;
}

// ---------------- embedding ----------------
__global__ void embed_k(const int* __restrict__ raw,
                        const float* __restrict__ tok,
                        const float* __restrict__ pos,
                        float* __restrict__ x) {
    int r = blockIdx.x;
    int t = r % TT;
    int idx = g_is64 ? raw[2 * r] : raw[r];
    const float* te = tok + (size_t)idx * EDIM;
    const float* pe = pos + (size_t)t * EDIM;
    float* xr = x + (size_t)r * EDIM;
    for (int e = threadIdx.x; e < EDIM; e += blockDim.x)
        xr[e] = te[e] + pe[e];
}

// ---------------- layernorm (output tf32-rounded: feeds MMA A operand) ----------------
__global__ void ln_k(const float* __restrict__ x,
                     const float* __restrict__ g,
                     const float* __restrict__ b,
                     float* __restrict__ y, int N) {
    int r = blockIdx.x;
    const float* xr = x + (size_t)r * N;
    float s = 0.f, s2 = 0.f;
    for (int i = threadIdx.x; i < N; i += blockDim.x) {
        float v = xr[i];
        s += v;
        s2 = fmaf(v, v, s2);
    }
    __shared__ float sh0[8], sh1[8];
    for (int o = 16; o > 0; o >>= 1) {
        s  += __shfl_down_sync(0xffffffffu, s, o);
        s2 += __shfl_down_sync(0xffffffffu, s2, o);
    }
    int w = threadIdx.x >> 5, lane = threadIdx.x & 31;
    if (lane == 0) { sh0[w] = s; sh1[w] = s2; }
    __syncthreads();
    if (threadIdx.x == 0) {
        float ts = 0.f, ts2 = 0.f;
        for (int i = 0; i < 8; i++) { ts += sh0[i]; ts2 += sh1[i]; }
        float mu = ts / (float)N;
        float var = ts2 / (float)N - mu * mu;
        sh0[0] = mu;
        sh1[0] = rsqrtf(var + 1e-5f);
    }
    __syncthreads();
    float mu = sh0[0], rstd = sh1[0];
    float* yr = y + (size_t)r * N;
    for (int i = threadIdx.x; i < N; i += blockDim.x)
        yr[i] = tf32rn((xr[i] - mu) * rstd * g[i] + b[i]);
}

// ---------------- tensor-core GEMM via mma.sync tf32 + ldmatrix ----------------
// C[1024, *] = A[1024, K] @ B[K, Nc]  (B row-major, direct)
// ksplit==1: blockIdx.z selects B0/B1/B2, out col offset z*zoff (fused QKV).
// ksplit>1 : blockIdx.z = K-split index; raw partial store at C[(z*MM+row)*ldc+col].
// mode 0: plain  1: +bias  2: relu(+bias), tf32-rounded  3: +bias +residual  4: partial
#define BKK 32
#define AST 36
#define BST 136
#define A_F (128 * AST)
#define B_F (BKK * BST)
#define STAGE_F (A_F + B_F)
#define DSMEM (2 * STAGE_F * 4)   // 71680 B

__device__ __forceinline__ void load_slab(const float* __restrict__ A,
                                          const float* __restrict__ B,
                                          int Nc, int lda, int kend,
                                          int bm, int bn, int k0,
                                          uint32_t sA, uint32_t sB, int tid) {
#pragma unroll
    for (int i = 0; i < 4; i++) {
        int c = tid + i * 256;
        int row = c >> 3;
        int c4  = c & 7;
        int gk = k0 + c4 * 4;
        uint32_t off = sA + (uint32_t)(row * AST + c4 * 4) * 4;
        if (gk < kend) cpa16(off, A + (size_t)(bm + row) * lda + gk);
        else           zfill16(off);
    }
#pragma unroll
    for (int i = 0; i < 4; i++) {
        int c = tid + i * 256;
        int row = c >> 5;
        int c4  = c & 31;
        int gk = k0 + row;
        int col = bn + c4 * 4;
        uint32_t off = sB + (uint32_t)(row * BST + c4 * 4) * 4;
        if (gk < kend && col < Nc) cpa16(off, B + (size_t)gk * Nc + col);
        else                       zfill16(off);
    }
}

__global__ void __launch_bounds__(256, 2)
tgemm_k(const float* __restrict__ A,
        const float* __restrict__ B0, const float* __restrict__ B1,
        const float* __restrict__ B2,
        const float* __restrict__ bias, const float* __restrict__ res,
        float* __restrict__ C, int Nc, int K, int ldc, int zoff,
        int mode, int ksplit) {
    extern __shared__ float smf[];

    int z = blockIdx.z;
    const float* Bm;
    int coff, kb, ke;
    size_t rowoff_out;
    if (ksplit > 1) {
        Bm = B0; coff = 0;
        int chunk = (K + ksplit - 1) / ksplit;
        kb = z * chunk;
        ke = min(K, kb + chunk);
        rowoff_out = (size_t)z * MM;
    } else {
        Bm = (z == 0) ? B0 : ((z == 1) ? B1 : B2);
        coff = z * zoff;
        kb = 0; ke = K;
        rowoff_out = 0;
    }

    int tid = threadIdx.x;
    int bn = blockIdx.x * 128, bm = blockIdx.y * 128;
    int warp = tid >> 5, lane = tid & 31;
    int wm = warp >> 2, wn = warp & 3;
    int g = lane >> 2, tig = lane & 3;

    // ldmatrix lane address pieces
    int lrow = (lane & 7) + ((lane & 8) ? 8 : 0);
    int lcoloff = (lane & 16) ? 4 : 0;

    uint32_t sbase = smem_u32(smf);

    float acc[4][4][4];
#pragma unroll
    for (int mt = 0; mt < 4; mt++)
#pragma unroll
        for (int nt = 0; nt < 4; nt++)
#pragma unroll
            for (int j = 0; j < 4; j++) acc[mt][nt][j] = 0.f;

    const int NS = (ke - kb + BKK - 1) / BKK;

    load_slab(A, Bm, Nc, K, ke, bm, bn, kb, sbase, sbase + A_F * 4, tid);
    asm volatile("cp.async.commit_group;" ::: "memory");

    for (int ksl = 0; ksl < NS; ksl++) {
        int st = ksl & 1;
        const float* As = smf + st * STAGE_F;
        const float* Bs = As + A_F;
        uint32_t sAs = sbase + (uint32_t)(st * STAGE_F) * 4;
        uint32_t abase = sAs + (uint32_t)((wm * 64 + lrow) * AST + lcoloff) * 4;

        int nk = ksl + 1;
        if (nk < NS) {
            int pst = nk & 1;
            load_slab(A, Bm, Nc, K, ke, bm, bn, kb + nk * BKK,
                      sbase + (uint32_t)(pst * STAGE_F) * 4,
                      sbase + (uint32_t)(pst * STAGE_F + A_F) * 4, tid);
        }
        asm volatile("cp.async.commit_group;" ::: "memory");
        asm volatile("cp.async.wait_group 1;" ::: "memory");
        __syncthreads();

#pragma unroll
        for (int ks = 0; ks < 4; ks++) {
            int k0 = ks * 8;
            uint32_t a[4][4];
#pragma unroll
            for (int mt = 0; mt < 4; mt++)
                ldsm4(a[mt], abase + (uint32_t)(mt * 16 * AST + k0) * 4);
            uint32_t b[4][2];
#pragma unroll
            for (int nt = 0; nt < 4; nt++) {
                const float* bp = Bs + (k0 + tig) * BST + wn * 32 + nt * 8 + g;
                b[nt][0] = tf32rn_u(bp[0]);
                b[nt][1] = tf32rn_u(bp[4 * BST]);
            }
#pragma unroll
            for (int mt = 0; mt < 4; mt++)
#pragma unroll
                for (int nt = 0; nt < 4; nt++)
                    mma_tf32(acc[mt][nt], a[mt], b[nt]);
        }
        __syncthreads();
    }

    // epilogue
    bool fullN = (bn + 128) <= Nc;
#pragma unroll
    for (int mt = 0; mt < 4; mt++) {
        size_t r0 = rowoff_out + bm + wm * 64 + mt * 16 + g;
        size_t r1 = r0 + 8;
#pragma unroll
        for (int nt = 0; nt < 4; nt++) {
            int lcol = bn + wn * 32 + nt * 8 + 2 * tig;
            int col = coff + lcol;
            float v0 = acc[mt][nt][0], v1 = acc[mt][nt][1];
            float v2 = acc[mt][nt][2], v3 = acc[mt][nt][3];
            if (fullN) {
                if (mode >= 1 && mode <= 3) {
                    float2 bb = *(const float2*)(bias + lcol);
                    v0 += bb.x; v1 += bb.y; v2 += bb.x; v3 += bb.y;
                }
                if (mode == 2) {
                    v0 = tf32rn(fmaxf(v0, 0.f)); v1 = tf32rn(fmaxf(v1, 0.f));
                    v2 = tf32rn(fmaxf(v2, 0.f)); v3 = tf32rn(fmaxf(v3, 0.f));
                }
                if (mode == 3) {
                    float2 q0 = *(const float2*)(res + r0 * ldc + col);
                    float2 q1 = *(const float2*)(res + r1 * ldc + col);
                    v0 += q0.x; v1 += q0.y; v2 += q1.x; v3 += q1.y;
                }
                *(float2*)(C + r0 * ldc + col) = make_float2(v0, v1);
                *(float2*)(C + r1 * ldc + col) = make_float2(v2, v3);
            } else {
                float vv[4] = {v0, v1, v2, v3};
                size_t rr[4] = {r0, r0, r1, r1};
                int cc[4] = {lcol, lcol + 1, lcol, lcol + 1};
#pragma unroll
                for (int j = 0; j < 4; j++) {
                    if (cc[j] >= Nc) continue;
                    float v = vv[j];
                    if (mode >= 1 && mode <= 3) v += bias[cc[j]];
                    if (mode == 2) v = tf32rn(fmaxf(v, 0.f));
                    if (mode == 3) v += res[rr[j] * ldc + coff + cc[j]];
                    C[rr[j] * ldc + coff + cc[j]] = v;
                }
            }
        }
    }
}

// ---------------- split-K reduce: out = sum_{s=0..3} part[s] + bias + res ----------------
__global__ void reduce4_k(const float* __restrict__ part,
                          const float* __restrict__ bias,
                          const float* __restrict__ res,
                          float* __restrict__ out, int N) {
    int r = blockIdx.x;
    const float* p0 = part + (size_t)r * N;
    const float* p1 = p0 + (size_t)MM * N;
    const float* p2 = p1 + (size_t)MM * N;
    const float* p3 = p2 + (size_t)MM * N;
    const float* rr = res + (size_t)r * N;
    float* o = out + (size_t)r * N;
    for (int c = threadIdx.x; c < N; c += blockDim.x) {
        float v = ((p0[c] + p1[c]) + (p2[c] + p3[c])) + bias[c] + rr[c];
        o[c] = v;
    }
}

// ---------------- attention ----------------
__global__ void __launch_bounds__(128)
attn_k(const float* __restrict__ qkv, float* __restrict__ att) {
    __shared__ float ks[TT][HS + 1];
    __shared__ float vs[TT][HS + 1];

    int bh = blockIdx.x;
    int b = bh / NH, h = bh % NH;
    int t = threadIdx.x;
    const size_t rbase = (size_t)b * TT * QKVN;
    const int hoff = h * HS;

    for (int idx = t; idx < TT * HS; idx += 128) {
        int s = idx / HS, d = idx % HS;
        ks[s][d] = qkv[rbase + (size_t)s * QKVN + HH + hoff + d];
        vs[s][d] = qkv[rbase + (size_t)s * QKVN + 2 * HH + hoff + d];
    }
    __syncthreads();

    float qreg[HS];
#pragma unroll
    for (int d = 0; d < HS; d++)
        qreg[d] = qkv[rbase + (size_t)t * QKVN + hoff + d];

    float m = -1e30f, l = 0.f;
    float out[HS];
#pragma unroll
    for (int d = 0; d < HS; d++) out[d] = 0.f;

    for (int s = 0; s <= t; s++) {
        float dot = 0.f;
#pragma unroll
        for (int d = 0; d < HS; d++)
            dot = fmaf(qreg[d], ks[s][d], dot);
        float sc = dot * ATT_SCALE;
        float mn = fmaxf(m, sc);
        float corr = expf(m - mn);
        float p = expf(sc - mn);
        l = l * corr + p;
#pragma unroll
        for (int d = 0; d < HS; d++)
            out[d] = out[d] * corr + p * vs[s][d];
        m = mn;
    }
    float inv = 1.f / l;
    size_t obase = (size_t)(b * TT + t) * HH + hoff;
#pragma unroll
    for (int d = 0; d < HS; d++)
        att[obase + d] = tf32rn(out[d] * inv);
}

// ---------------- launcher ----------------
extern "C" void kernel_launch(void* const* d_in, const int* in_sizes, int n_in,
                              void* d_out, int out_size) {
    (void)in_sizes; (void)n_in; (void)out_size;
    const int*   index = (const int*)  d_in[0];
    const float* tok   = (const float*)d_in[1];
    const float* pos   = (const float*)d_in[2];
    const float* wq    = (const float*)d_in[3];
    const float* wk    = (const float*)d_in[4];
    const float* wv    = (const float*)d_in[5];
    const float* wo    = (const float*)d_in[6];
    const float* bo    = (const float*)d_in[7];
    const float* ln1g  = (const float*)d_in[8];
    const float* ln1b  = (const float*)d_in[9];
    const float* ln2g  = (const float*)d_in[10];
    const float* ln2b  = (const float*)d_in[11];
    const float* w1    = (const float*)d_in[12];
    const float* b1    = (const float*)d_in[13];
    const float* w2    = (const float*)d_in[14];
    const float* b2    = (const float*)d_in[15];
    const float* lnfg  = (const float*)d_in[16];
    const float* lnfb  = (const float*)d_in[17];
    const float* wh    = (const float*)d_in[18];
    const float* bh    = (const float*)d_in[19];
    float* out = (float*)d_out;

    float *x, *y, *qkv, *att, *hb, *part;
    cudaGetSymbolAddress((void**)&x,    g_x);
    cudaGetSymbolAddress((void**)&y,    g_y);
    cudaGetSymbolAddress((void**)&qkv,  g_qkv);
    cudaGetSymbolAddress((void**)&att,  g_att);
    cudaGetSymbolAddress((void**)&hb,   g_h);
    cudaGetSymbolAddress((void**)&part, g_part);

    cudaFuncSetAttribute(tgemm_k, cudaFuncAttributeMaxDynamicSharedMemorySize, DSMEM);

    detect_k<<<1, 256>>>(index);
    embed_k<<<MM, 256>>>(index, tok, pos, x);

    for (int l = 0; l < NL; l++) {
        const float* pwq = wq + (size_t)l * EDIM * HH;
        const float* pwk = wk + (size_t)l * EDIM * HH;
        const float* pwv = wv + (size_t)l * EDIM * HH;
        const float* pwo = wo + (size_t)l * HH * EDIM;
        const float* pbo = bo + (size_t)l * EDIM;
        const float* g1  = ln1g + (size_t)l * EDIM;
        const float* be1 = ln1b + (size_t)l * EDIM;
        const float* g2  = ln2g + (size_t)l * EDIM;
        const float* be2 = ln2b + (size_t)l * EDIM;
        const float* pw1 = w1 + (size_t)l * EDIM * FF;
        const float* pb1 = b1 + (size_t)l * FF;
        const float* pw2 = w2 + (size_t)l * FF * EDIM;
        const float* pb2 = b2 + (size_t)l * EDIM;

        ln_k<<<MM, 256>>>(x, g1, be1, y, EDIM);

        // fused QKV (z = weight select)
        tgemm_k<<<dim3(9, 8, 3), 256, DSMEM>>>(
            y, pwq, pwk, pwv, nullptr, nullptr, qkv, HH, EDIM, QKVN, HH, 0, 1);

        attn_k<<<BB * NH, 128>>>(qkv, att);

        // wo: split-K x4 -> partials -> reduce(+bias+residual)
        tgemm_k<<<dim3(9, 8, 4), 256, DSMEM>>>(
            att, pwo, nullptr, nullptr, nullptr, nullptr, part, EDIM, HH, EDIM, 0, 4, 4);
        reduce4_k<<<MM, 256>>>(part, pbo, x, x, EDIM);

        ln_k<<<MM, 256>>>(x, g2, be2, y, EDIM);

        // w1: relu(y @ w1 + b1)
        tgemm_k<<<dim3(36, 8, 1), 256, DSMEM>>>(
            y, pw1, nullptr, nullptr, pb1, nullptr, hb, FF, EDIM, FF, 0, 2, 1);

        // w2: split-K x4 -> partials -> reduce(+bias+residual)
        tgemm_k<<<dim3(9, 8, 4), 256, DSMEM>>>(
            hb, pw2, nullptr, nullptr, nullptr, nullptr, part, EDIM, FF, EDIM, 0, 4, 4);
        reduce4_k<<<MM, 256>>>(part, pb2, x, x, EDIM);
    }

    ln_k<<<MM, 256>>>(x, lnfg, lnfb, y, EDIM);
    tgemm_k<<<dim3(352, 8, 1), 256, DSMEM>>>(
        y, wh, nullptr, nullptr, bh, nullptr, out, VOC, EDIM, VOC, 0, 1, 1);
}

// round 6
// speedup vs baseline: 6.2182x; 1.0705x over previous
#include <cuda_runtime.h>
#include <cstdint>
#include <math.h>

// ---------------- problem constants ----------------
#define EDIM 1140
#define HH   1120
#define NH   32
#define HS   35
#define NL   36
#define VOC  45000
#define TT   128
#define BB   8
#define MM   (BB*TT)       // 1024
#define FF   (4*EDIM)      // 4560
#define QKVN (3*HH)        // 3360
#define ATT_SCALE 0.16903085094570331f

// ---------------- scratch (device globals) ----------------
__device__ float g_x[MM * EDIM];
__device__ float g_y[MM * EDIM];
__device__ float g_qkv[MM * QKVN];
__device__ float g_att[MM * HH];
__device__ float g_h[MM * FF];
__device__ float g_part[4 * MM * EDIM];   // split-K partials
__device__ int   g_is64;

// ---------------- helpers ----------------
__device__ __forceinline__ uint32_t smem_u32(const void* p) {
    uint32_t a;
    asm("{ .reg .u64 t; cvta.to.shared.u64 t, %1; cvt.u32.u64 %0, t; }" : "=r"(a) : "l"(p));
    return a;
}
__device__ __forceinline__ float tf32rn(float x) {
    uint32_t u; asm("cvt.rn.tf32.f32 %0, %1;" : "=r"(u) : "f"(x));
    return __uint_as_float(u);
}
__device__ __forceinline__ uint32_t tf32rn_u(float x) {
    uint32_t u; asm("cvt.rn.tf32.f32 %0, %1;" : "=r"(u) : "f"(x));
    return u;
}
__device__ __forceinline__ void cpa16(uint32_t s, const void* g) {
    asm volatile("cp.async.cg.shared.global [%0], [%1], 16;" :: "r"(s), "l"(g) : "memory");
}
__device__ __forceinline__ void zfill16(uint32_t s) {
    asm volatile("st.shared.v4.b32 [%0], {%1,%1,%1,%1};" :: "r"(s), "r"(0) : "memory");
}
__device__ __forceinline__ void mma_tf32(float* d, const uint32_t* a, const uint32_t* b) {
    asm volatile(
        "mma.sync.aligned.m16n8k8.row.col.f32.tf32.tf32.f32 "
        "{%0,%1,%2,%3}, {%4,%5,%6,%7}, {%8,%9}, {%0,%1,%2,%3};"
        : "+f"(d[0]), "+f"(d[1]), "+f"(d[2]), "+f"(d[3])
        : "r"(a[0]), "r"(a[1]), "r"(a[2]), "r"(a[3]), "r"(b[0]), "r"(b[1]));
}
__device__ __forceinline__ void ldsm4(uint32_t* r, uint32_t a) {
    asm volatile("ldmatrix.sync.aligned.m8n8.x4.shared.b16 {%0,%1,%2,%3}, [%4];"
        : "=r"(r[0]), "=r"(r[1]), "=r"(r[2]), "=r"(r[3]) : "r"(a));
}

// ---------------- index dtype detection ----------------
__global__ void detect_k(const int* __restrict__ raw) {
    __shared__ int any;
    if (threadIdx.x == 0) any = 0;
    __syncthreads();
    int local = 0;
    for (int i = threadIdx.x; i < 512; i += blockDim.x)
        if (raw[2 * i + 1] != 0) local = 1;
    if (local) atomicOr(&any, 1);
    __syncthreads();
    if (threadIdx.x == 0) g_is64 = any ? 0 : 1;
}

// ---------------- embedding ----------------
__global__ void embed_k(const int* __restrict__ raw,
                        const float* __restrict__ tok,
                        const float* __restrict__ pos,
                        float* __restrict__ x) {
    int r = blockIdx.x;
    int t = r % TT;
    int idx = g_is64 ? raw[2 * r] : raw[r];
    const float* te = tok + (size_t)idx * EDIM;
    const float* pe = pos + (size_t)t * EDIM;
    float* xr = x + (size_t)r * EDIM;
    for (int e = threadIdx.x; e < EDIM; e += blockDim.x)
        xr[e] = te[e] + pe[e];
}

// ---------------- layernorm (output tf32-rounded: feeds MMA A operand) ----------------
__global__ void ln_k(const float* __restrict__ x,
                     const float* __restrict__ g,
                     const float* __restrict__ b,
                     float* __restrict__ y, int N) {
    int r = blockIdx.x;
    const float* xr = x + (size_t)r * N;
    float s = 0.f, s2 = 0.f;
    for (int i = threadIdx.x; i < N; i += blockDim.x) {
        float v = xr[i];
        s += v;
        s2 = fmaf(v, v, s2);
    }
    __shared__ float sh0[8], sh1[8];
    for (int o = 16; o > 0; o >>= 1) {
        s  += __shfl_down_sync(0xffffffffu, s, o);
        s2 += __shfl_down_sync(0xffffffffu, s2, o);
    }
    int w = threadIdx.x >> 5, lane = threadIdx.x & 31;
    if (lane == 0) { sh0[w] = s; sh1[w] = s2; }
    __syncthreads();
    if (threadIdx.x == 0) {
        float ts = 0.f, ts2 = 0.f;
        for (int i = 0; i < 8; i++) { ts += sh0[i]; ts2 += sh1[i]; }
        float mu = ts / (float)N;
        float var = ts2 / (float)N - mu * mu;
        sh0[0] = mu;
        sh1[0] = rsqrtf(var + 1e-5f);
    }
    __syncthreads();
    float mu = sh0[0], rstd = sh1[0];
    float* yr = y + (size_t)r * N;
    for (int i = threadIdx.x; i < N; i += blockDim.x)
        yr[i] = tf32rn((xr[i] - mu) * rstd * g[i] + b[i]);
}

// ---------------- tensor-core GEMM: tf32 mma.sync + ldmatrix + 3-stage cp.async ----------------
// C[1024, *] = A[1024, K] @ B[K, Nc]  (B row-major, direct)
// ksplit==1: blockIdx.z selects B0/B1/B2, out col offset z*zoff (fused QKV).
// ksplit>1 : blockIdx.z = K-split index; raw partial store at C[(z*MM+row)*ldc+col].
// mode 0: plain  1: +bias  2: relu(+bias), tf32-rounded  3: +bias +residual  4: partial
#define BKK 32
#define AST 36
#define BST 136
#define A_F (128 * AST)
#define B_F (BKK * BST)
#define STAGE_F (A_F + B_F)          // 8960 floats = 35840 B
#define NSTG 3
#define DSMEM (NSTG * STAGE_F * 4)   // 107520 B  -> 2 CTAs/SM = 215 KB

__device__ __forceinline__ void load_slab(const float* __restrict__ A,
                                          const float* __restrict__ B,
                                          int Nc, int lda, int kend,
                                          int bm, int bn, int k0,
                                          uint32_t sA, uint32_t sB, int tid) {
#pragma unroll
    for (int i = 0; i < 4; i++) {
        int c = tid + i * 256;
        int row = c >> 3;
        int c4  = c & 7;
        int gk = k0 + c4 * 4;
        uint32_t off = sA + (uint32_t)(row * AST + c4 * 4) * 4;
        if (gk < kend) cpa16(off, A + (size_t)(bm + row) * lda + gk);
        else           zfill16(off);
    }
#pragma unroll
    for (int i = 0; i < 4; i++) {
        int c = tid + i * 256;
        int row = c >> 5;
        int c4  = c & 31;
        int gk = k0 + row;
        int col = bn + c4 * 4;
        uint32_t off = sB + (uint32_t)(row * BST + c4 * 4) * 4;
        if (gk < kend && col < Nc) cpa16(off, B + (size_t)gk * Nc + col);
        else                       zfill16(off);
    }
}

__global__ void __launch_bounds__(256, 2)
tgemm_k(const float* __restrict__ A,
        const float* __restrict__ B0, const float* __restrict__ B1,
        const float* __restrict__ B2,
        const float* __restrict__ bias, const float* __restrict__ res,
        float* __restrict__ C, int Nc, int K, int ldc, int zoff,
        int mode, int ksplit) {
    extern __shared__ float smf[];

    int z = blockIdx.z;
    const float* Bm;
    int coff, kb, ke;
    size_t rowoff_out;
    if (ksplit > 1) {
        Bm = B0; coff = 0;
        int chunk = (K + ksplit - 1) / ksplit;
        kb = z * chunk;
        ke = min(K, kb + chunk);
        rowoff_out = (size_t)z * MM;
    } else {
        Bm = (z == 0) ? B0 : ((z == 1) ? B1 : B2);
        coff = z * zoff;
        kb = 0; ke = K;
        rowoff_out = 0;
    }

    int tid = threadIdx.x;
    int bn = blockIdx.x * 128, bm = blockIdx.y * 128;
    int warp = tid >> 5, lane = tid & 31;
    int wm = warp >> 2, wn = warp & 3;
    int g = lane >> 2, tig = lane & 3;

    int lrow = (lane & 7) + ((lane & 8) ? 8 : 0);
    int lcoloff = (lane & 16) ? 4 : 0;

    uint32_t sbase = smem_u32(smf);

    float acc[4][4][4];
#pragma unroll
    for (int mt = 0; mt < 4; mt++)
#pragma unroll
        for (int nt = 0; nt < 4; nt++)
#pragma unroll
            for (int j = 0; j < 4; j++) acc[mt][nt][j] = 0.f;

    const int NS = (ke - kb + BKK - 1) / BKK;

    // prologue: stages 0 and 1 in flight (2 committed groups)
    load_slab(A, Bm, Nc, K, ke, bm, bn, kb, sbase, sbase + A_F * 4, tid);
    asm volatile("cp.async.commit_group;" ::: "memory");
    if (NS > 1)
        load_slab(A, Bm, Nc, K, ke, bm, bn, kb + BKK,
                  sbase + (uint32_t)STAGE_F * 4,
                  sbase + (uint32_t)(STAGE_F + A_F) * 4, tid);
    asm volatile("cp.async.commit_group;" ::: "memory");
    asm volatile("cp.async.wait_group 1;" ::: "memory");   // stage 0 ready
    __syncthreads();

    int cst = 0;   // compute stage
    int lst = 2;   // load stage for slab ksl+2

    for (int ksl = 0; ksl < NS; ksl++) {
        const float* As = smf + cst * STAGE_F;
        const float* Bs = As + A_F;
        uint32_t sAs = sbase + (uint32_t)(cst * STAGE_F) * 4;
        uint32_t abase = sAs + (uint32_t)((wm * 64 + lrow) * AST + lcoloff) * 4;

        // compute first: feed the tensor pipe before LSU work
#pragma unroll
        for (int ks = 0; ks < 4; ks++) {
            int k0 = ks * 8;
            uint32_t a[4][4];
#pragma unroll
            for (int mt = 0; mt < 4; mt++)
                ldsm4(a[mt], abase + (uint32_t)(mt * 16 * AST + k0) * 4);
            uint32_t b[4][2];
#pragma unroll
            for (int nt = 0; nt < 4; nt++) {
                const float* bp = Bs + (k0 + tig) * BST + wn * 32 + nt * 8 + g;
                b[nt][0] = tf32rn_u(bp[0]);
                b[nt][1] = tf32rn_u(bp[4 * BST]);
            }
#pragma unroll
            for (int mt = 0; mt < 4; mt++)
#pragma unroll
                for (int nt = 0; nt < 4; nt++)
                    mma_tf32(acc[mt][nt], a[mt], b[nt]);
        }

        // issue loads for slab ksl+2 into stage lst (consumed at ksl-1; one
        // barrier ago + >=200cyc cp.async flight => safe)
        if (ksl + 2 < NS) {
            load_slab(A, Bm, Nc, K, ke, bm, bn, kb + (ksl + 2) * BKK,
                      sbase + (uint32_t)(lst * STAGE_F) * 4,
                      sbase + (uint32_t)(lst * STAGE_F + A_F) * 4, tid);
        }
        asm volatile("cp.async.commit_group;" ::: "memory");
        asm volatile("cp.async.wait_group 1;" ::: "memory");  // stage ksl+1 ready
        __syncthreads();

        if (++cst == NSTG) cst = 0;
        if (++lst == NSTG) lst = 0;
    }

    // epilogue
    bool fullN = (bn + 128) <= Nc;
#pragma unroll
    for (int mt = 0; mt < 4; mt++) {
        size_t r0 = rowoff_out + bm + wm * 64 + mt * 16 + g;
        size_t r1 = r0 + 8;
#pragma unroll
        for (int nt = 0; nt < 4; nt++) {
            int lcol = bn + wn * 32 + nt * 8 + 2 * tig;
            int col = coff + lcol;
            float v0 = acc[mt][nt][0], v1 = acc[mt][nt][1];
            float v2 = acc[mt][nt][2], v3 = acc[mt][nt][3];
            if (fullN) {
                if (mode >= 1 && mode <= 3) {
                    float2 bb = *(const float2*)(bias + lcol);
                    v0 += bb.x; v1 += bb.y; v2 += bb.x; v3 += bb.y;
                }
                if (mode == 2) {
                    v0 = tf32rn(fmaxf(v0, 0.f)); v1 = tf32rn(fmaxf(v1, 0.f));
                    v2 = tf32rn(fmaxf(v2, 0.f)); v3 = tf32rn(fmaxf(v3, 0.f));
                }
                if (mode == 3) {
                    float2 q0 = *(const float2*)(res + r0 * ldc + col);
                    float2 q1 = *(const float2*)(res + r1 * ldc + col);
                    v0 += q0.x; v1 += q0.y; v2 += q1.x; v3 += q1.y;
                }
                *(float2*)(C + r0 * ldc + col) = make_float2(v0, v1);
                *(float2*)(C + r1 * ldc + col) = make_float2(v2, v3);
            } else {
                float vv[4] = {v0, v1, v2, v3};
                size_t rr[4] = {r0, r0, r1, r1};
                int cc[4] = {lcol, lcol + 1, lcol, lcol + 1};
#pragma unroll
                for (int j = 0; j < 4; j++) {
                    if (cc[j] >= Nc) continue;
                    float v = vv[j];
                    if (mode >= 1 && mode <= 3) v += bias[cc[j]];
                    if (mode == 2) v = tf32rn(fmaxf(v, 0.f));
                    if (mode == 3) v += res[rr[j] * ldc + coff + cc[j]];
                    C[rr[j] * ldc + coff + cc[j]] = v;
                }
            }
        }
    }
}

// ---------------- split-K reduce: out = sum_{s=0..3} part[s] + bias + res ----------------
__global__ void reduce4_k(const float* __restrict__ part,
                          const float* __restrict__ bias,
                          const float* __restrict__ res,
                          float* __restrict__ out, int N) {
    int r = blockIdx.x;
    const float* p0 = part + (size_t)r * N;
    const float* p1 = p0 + (size_t)MM * N;
    const float* p2 = p1 + (size_t)MM * N;
    const float* p3 = p2 + (size_t)MM * N;
    const float* rr = res + (size_t)r * N;
    float* o = out + (size_t)r * N;
    for (int c = threadIdx.x; c < N; c += blockDim.x) {
        float v = ((p0[c] + p1[c]) + (p2[c] + p3[c])) + bias[c] + rr[c];
        o[c] = v;
    }
}

// ---------------- attention ----------------
__global__ void __launch_bounds__(128)
attn_k(const float* __restrict__ qkv, float* __restrict__ att) {
    __shared__ float ks[TT][HS + 1];
    __shared__ float vs[TT][HS + 1];

    int bh = blockIdx.x;
    int b = bh / NH, h = bh % NH;
    int t = threadIdx.x;
    const size_t rbase = (size_t)b * TT * QKVN;
    const int hoff = h * HS;

    for (int idx = t; idx < TT * HS; idx += 128) {
        int s = idx / HS, d = idx % HS;
        ks[s][d] = qkv[rbase + (size_t)s * QKVN + HH + hoff + d];
        vs[s][d] = qkv[rbase + (size_t)s * QKVN + 2 * HH + hoff + d];
    }
    __syncthreads();

    float qreg[HS];
#pragma unroll
    for (int d = 0; d < HS; d++)
        qreg[d] = qkv[rbase + (size_t)t * QKVN + hoff + d];

    float m = -1e30f, l = 0.f;
    float out[HS];
#pragma unroll
    for (int d = 0; d < HS; d++) out[d] = 0.f;

    for (int s = 0; s <= t; s++) {
        float dot = 0.f;
#pragma unroll
        for (int d = 0; d < HS; d++)
            dot = fmaf(qreg[d], ks[s][d], dot);
        float sc = dot * ATT_SCALE;
        float mn = fmaxf(m, sc);
        float corr = expf(m - mn);
        float p = expf(sc - mn);
        l = l * corr + p;
#pragma unroll
        for (int d = 0; d < HS; d++)
            out[d] = out[d] * corr + p * vs[s][d];
        m = mn;
    }
    float inv = 1.f / l;
    size_t obase = (size_t)(b * TT + t) * HH + hoff;
#pragma unroll
    for (int d = 0; d < HS; d++)
        att[obase + d] = tf32rn(out[d] * inv);
}

// ---------------- launcher ----------------
extern "C" void kernel_launch(void* const* d_in, const int* in_sizes, int n_in,
                              void* d_out, int out_size) {
    (void)in_sizes; (void)n_in; (void)out_size;
    const int*   index = (const int*)  d_in[0];
    const float* tok   = (const float*)d_in[1];
    const float* pos   = (const float*)d_in[2];
    const float* wq    = (const float*)d_in[3];
    const float* wk    = (const float*)d_in[4];
    const float* wv    = (const float*)d_in[5];
    const float* wo    = (const float*)d_in[6];
    const float* bo    = (const float*)d_in[7];
    const float* ln1g  = (const float*)d_in[8];
    const float* ln1b  = (const float*)d_in[9];
    const float* ln2g  = (const float*)d_in[10];
    const float* ln2b  = (const float*)d_in[11];
    const float* w1    = (const float*)d_in[12];
    const float* b1    = (const float*)d_in[13];
    const float* w2    = (const float*)d_in[14];
    const float* b2    = (const float*)d_in[15];
    const float* lnfg  = (const float*)d_in[16];
    const float* lnfb  = (const float*)d_in[17];
    const float* wh    = (const float*)d_in[18];
    const float* bh    = (const float*)d_in[19];
    float* out = (float*)d_out;

    float *x, *y, *qkv, *att, *hb, *part;
    cudaGetSymbolAddress((void**)&x,    g_x);
    cudaGetSymbolAddress((void**)&y,    g_y);
    cudaGetSymbolAddress((void**)&qkv,  g_qkv);
    cudaGetSymbolAddress((void**)&att,  g_att);
    cudaGetSymbolAddress((void**)&hb,   g_h);
    cudaGetSymbolAddress((void**)&part, g_part);

    cudaFuncSetAttribute(tgemm_k, cudaFuncAttributeMaxDynamicSharedMemorySize, DSMEM);

    detect_k<<<1, 256>>>(index);
    embed_k<<<MM, 256>>>(index, tok, pos, x);

    for (int l = 0; l < NL; l++) {
        const float* pwq = wq + (size_t)l * EDIM * HH;
        const float* pwk = wk + (size_t)l * EDIM * HH;
        const float* pwv = wv + (size_t)l * EDIM * HH;
        const float* pwo = wo + (size_t)l * HH * EDIM;
        const float* pbo = bo + (size_t)l * EDIM;
        const float* g1  = ln1g + (size_t)l * EDIM;
        const float* be1 = ln1b + (size_t)l * EDIM;
        const float* g2  = ln2g + (size_t)l * EDIM;
        const float* be2 = ln2b + (size_t)l * EDIM;
        const float* pw1 = w1 + (size_t)l * EDIM * FF;
        const float* pb1 = b1 + (size_t)l * FF;
        const float* pw2 = w2 + (size_t)l * FF * EDIM;
        const float* pb2 = b2 + (size_t)l * EDIM;

        ln_k<<<MM, 256>>>(x, g1, be1, y, EDIM);

        // fused QKV (z = weight select)
        tgemm_k<<<dim3(9, 8, 3), 256, DSMEM>>>(
            y, pwq, pwk, pwv, nullptr, nullptr, qkv, HH, EDIM, QKVN, HH, 0, 1);

        attn_k<<<BB * NH, 128>>>(qkv, att);

        // wo: split-K x4 -> partials -> reduce(+bias+residual)
        tgemm_k<<<dim3(9, 8, 4), 256, DSMEM>>>(
            att, pwo, nullptr, nullptr, nullptr, nullptr, part, EDIM, HH, EDIM, 0, 4, 4);
        reduce4_k<<<MM, 256>>>(part, pbo, x, x, EDIM);

        ln_k<<<MM, 256>>>(x, g2, be2, y, EDIM);

        // w1: relu(y @ w1 + b1)
        tgemm_k<<<dim3(36, 8, 1), 256, DSMEM>>>(
            y, pw1, nullptr, nullptr, pb1, nullptr, hb, FF, EDIM, FF, 0, 2, 1);

        // w2: split-K x4 -> partials -> reduce(+bias+residual)
        tgemm_k<<<dim3(9, 8, 4), 256, DSMEM>>>(
            hb, pw2, nullptr, nullptr, nullptr, nullptr, part, EDIM, FF, EDIM, 0, 4, 4);
        reduce4_k<<<MM, 256>>>(part, pb2, x, x, EDIM);
    }

    ln_k<<<MM, 256>>>(x, lnfg, lnfb, y, EDIM);
    tgemm_k<<<dim3(352, 8, 1), 256, DSMEM>>>(
        y, wh, nullptr, nullptr, bh, nullptr, out, VOC, EDIM, VOC, 0, 1, 1);
}

// round 7
// speedup vs baseline: 7.8534x; 1.2630x over previous
#include <cuda_runtime.h>
#include <cuda_fp16.h>
#include <cstdint>
#include <math.h>

// ---------------- problem constants ----------------
#define EDIM 1140
#define KP   1144            // EDIM padded to mult of 8 (fp16 16B chunks)
#define HH   1120
#define NH   32
#define HS   35
#define NL   36
#define VOC  45000
#define TT   128
#define BB   8
#define MM   1024
#define FF   4560
#define QKVN 3360
#define ATT_SCALE 0.16903085094570331f

// ---------------- converted-weight layout (fp16, transposed [N][K]) ----------------
#define SZQ  (1120*KP)
#define OFF_QKV ((size_t)0)
#define SZWO (1140*1120)
#define OFF_WO  ((size_t)NL*3*SZQ)
#define SZW1 (4560*KP)
#define OFF_W1  (OFF_WO + (size_t)NL*SZWO)
#define SZW2 (1140*4560)
#define OFF_W2  (OFF_W1 + (size_t)NL*SZW1)
#define OFF_WH  (OFF_W2 + (size_t)NL*SZW2)
#define WTOT    (OFF_WH + (size_t)VOC*KP)   // 610,764,480 halfs

// ---------------- scratch (device globals) ----------------
__device__ float  g_x[MM * EDIM];
__device__ float  g_qkv[MM * QKVN];
__device__ float  g_part[4 * MM * EDIM];
__device__ __half g_y16[MM * KP];
__device__ __half g_att16[MM * HH];
__device__ __half g_h16[MM * FF];
__device__ __half g_w16[WTOT];
__device__ int    g_is64;

// ---------------- helpers ----------------
__device__ __forceinline__ uint32_t smem_u32(const void* p) {
    uint32_t a;
    asm("{ .reg .u64 t; cvta.to.shared.u64 t, %1; cvt.u32.u64 %0, t; }" : "=r"(a) : "l"(p));
    return a;
}
__device__ __forceinline__ void cpa16(uint32_t s, const void* g) {
    asm volatile("cp.async.cg.shared.global [%0], [%1], 16;" :: "r"(s), "l"(g) : "memory");
}
__device__ __forceinline__ void zfill16(uint32_t s) {
    asm volatile("st.shared.v4.b32 [%0], {%1,%1,%1,%1};" :: "r"(s), "r"(0) : "memory");
}
__device__ __forceinline__ void mma_f16(float* d, const uint32_t* a, const uint32_t* b) {
    asm volatile(
        "mma.sync.aligned.m16n8k16.row.col.f32.f16.f16.f32 "
        "{%0,%1,%2,%3}, {%4,%5,%6,%7}, {%8,%9}, {%0,%1,%2,%3};"
        : "+f"(d[0]), "+f"(d[1]), "+f"(d[2]), "+f"(d[3])
        : "r"(a[0]), "r"(a[1]), "r"(a[2]), "r"(a[3]), "r"(b[0]), "r"(b[1]));
}
__device__ __forceinline__ void ldsm4(uint32_t* r, uint32_t a) {
    asm volatile("ldmatrix.sync.aligned.m8n8.x4.shared.b16 {%0,%1,%2,%3}, [%4];"
        : "=r"(r[0]), "=r"(r[1]), "=r"(r[2]), "=r"(r[3]) : "r"(a));
}

// ---------------- index dtype detection ----------------
__global__ void detect_k(const int* __restrict__ raw) {
    __shared__ int any;
    if (threadIdx.x == 0) any = 0;
    __syncthreads();
    int local = 0;
    for (int i = threadIdx.x; i < 512; i += blockDim.x)
        if (raw[2 * i + 1] != 0) local = 1;
    if (local) atomicOr(&any, 1);
    __syncthreads();
    if (threadIdx.x == 0) g_is64 = any ? 0 : 1;
}

// ---------------- weight convert: f32 [K][N] -> fp16 [N][KPad] (RN), zero K-pad ----------------
__global__ void convT_k(const float* __restrict__ in, __half* __restrict__ out,
                        int K, int N, int KPad, size_t inLs, size_t outLs) {
    in  += (size_t)blockIdx.z * inLs;
    out += (size_t)blockIdx.z * outLs;
    __shared__ float t[32][33];
    int bn = blockIdx.x * 32, bk = blockIdx.y * 32;
    int x = threadIdx.x, y = threadIdx.y;
#pragma unroll
    for (int i = 0; i < 32; i += 8) {
        int k = bk + y + i, n = bn + x;
        t[y + i][x] = (k < K && n < N) ? in[(size_t)k * N + n] : 0.f;
    }
    __syncthreads();
#pragma unroll
    for (int i = 0; i < 32; i += 8) {
        int n = bn + y + i, k = bk + x;
        if (n < N && k < KPad) out[(size_t)n * KPad + k] = __float2half_rn(t[x][y + i]);
    }
}

// ---------------- block row-LN from smem values -> y16 (fp16, zero-padded to KP) ----------------
__device__ __forceinline__ void row_ln_emit(const float* v, float s, float s2,
                                            const float* g, const float* b,
                                            __half* yrow) {
    __shared__ float sh0[8], sh1[8];
    for (int o = 16; o > 0; o >>= 1) {
        s  += __shfl_down_sync(0xffffffffu, s, o);
        s2 += __shfl_down_sync(0xffffffffu, s2, o);
    }
    int w = threadIdx.x >> 5, lane = threadIdx.x & 31;
    if (lane == 0) { sh0[w] = s; sh1[w] = s2; }
    __syncthreads();
    if (threadIdx.x == 0) {
        float ts = 0.f, ts2 = 0.f;
        for (int i = 0; i < 8; i++) { ts += sh0[i]; ts2 += sh1[i]; }
        float mu = ts / (float)EDIM;
        float var = ts2 / (float)EDIM - mu * mu;
        sh0[0] = mu;
        sh1[0] = rsqrtf(var + 1e-5f);
    }
    __syncthreads();
    float mu = sh0[0], rstd = sh1[0];
    for (int c = threadIdx.x; c < KP; c += blockDim.x) {
        float o = (c < EDIM) ? (v[c] - mu) * rstd * g[c] + b[c] : 0.f;
        yrow[c] = __float2half_rn(o);
    }
}

// ---------------- embedding + LN1(layer0) ----------------
__global__ void embed_ln_k(const int* __restrict__ raw,
                           const float* __restrict__ tok,
                           const float* __restrict__ pos,
                           const float* __restrict__ g,
                           const float* __restrict__ b,
                           float* __restrict__ x, __half* __restrict__ y16) {
    __shared__ float v[EDIM];
    int r = blockIdx.x, t = r % TT;
    int idx = g_is64 ? raw[2 * r] : raw[r];
    const float* te = tok + (size_t)idx * EDIM;
    const float* pe = pos + (size_t)t * EDIM;
    float s = 0.f, s2 = 0.f;
    for (int c = threadIdx.x; c < EDIM; c += blockDim.x) {
        float val = te[c] + pe[c];
        v[c] = val;
        x[(size_t)r * EDIM + c] = val;
        s += val; s2 = fmaf(val, val, s2);
    }
    __syncthreads();
    row_ln_emit(v, s, s2, g, b, y16 + (size_t)r * KP);
}

// ---------------- split-K reduce + residual + bias -> x; then LN -> y16 ----------------
__global__ void reduce4ln_k(const float* __restrict__ part,
                            const float* __restrict__ bias,
                            float* __restrict__ x,
                            const float* __restrict__ g,
                            const float* __restrict__ b,
                            __half* __restrict__ y16) {
    __shared__ float v[EDIM];
    int r = blockIdx.x;
    const float* p0 = part + (size_t)r * EDIM;
    const float* p1 = p0 + (size_t)MM * EDIM;
    const float* p2 = p1 + (size_t)MM * EDIM;
    const float* p3 = p2 + (size_t)MM * EDIM;
    float* xr = x + (size_t)r * EDIM;
    float s = 0.f, s2 = 0.f;
    for (int c = threadIdx.x; c < EDIM; c += blockDim.x) {
        float val = ((p0[c] + p1[c]) + (p2[c] + p3[c])) + bias[c] + xr[c];
        xr[c] = val;
        v[c] = val;
        s += val; s2 = fmaf(val, val, s2);
    }
    __syncthreads();
    row_ln_emit(v, s, s2, g, b, y16 + (size_t)r * KP);
}

// ---------------- fp16 tensor-core GEMM ----------------
// C[1024, Nc] = A16[1024, K] @ B16t[Nc, K]^T  (both fp16, K-contiguous, lda = padded K)
// kchunk==0: blockIdx.z selects B0/B1/B2, output col offset z*zoff (fused QKV)
// kchunk>0 : blockIdx.z = split-K index, partial f32 at C[(z*MM+row)*ldc+col]
// mode 0: plain f32  1: +bias f32  2: relu(+bias) -> fp16 C16  4: raw partial f32
#define BKK 32
#define ASTH 40                         // smem pitch in halfs (80 B, ldsm conflict-free)
#define STG_H (2 * 128 * ASTH)          // A + B halfs per stage = 10240
#define NSTG 4
#define DSMEM (NSTG * STG_H * 2)        // 81920 B -> 2 CTAs/SM = 164 KB

__device__ __forceinline__ void load_slab_h(const __half* __restrict__ A,
                                            const __half* __restrict__ B,
                                            int Nc, int lda, int kend,
                                            int bm, int bn, int k0,
                                            uint32_t sA, uint32_t sB, int tid) {
#pragma unroll
    for (int i = 0; i < 2; i++) {                  // A: 128 rows x 32 k
        int c = tid + i * 256;
        int row = c >> 2;
        int kc = (c & 3) * 8;
        int gk = k0 + kc;
        uint32_t off = sA + (uint32_t)(row * ASTH + kc) * 2;
        if (gk < kend) cpa16(off, A + (size_t)(bm + row) * lda + gk);
        else           zfill16(off);
    }
#pragma unroll
    for (int i = 0; i < 2; i++) {                  // B: 128 n-rows x 32 k
        int c = tid + i * 256;
        int row = c >> 2;
        int kc = (c & 3) * 8;
        int gk = k0 + kc;
        uint32_t off = sB + (uint32_t)(row * ASTH + kc) * 2;
        if (gk < kend && (bn + row) < Nc) cpa16(off, B + (size_t)(bn + row) * lda + gk);
        else                              zfill16(off);
    }
}

__global__ void __launch_bounds__(256, 2)
hgemm_k(const __half* __restrict__ A,
        const __half* __restrict__ B0, const __half* __restrict__ B1,
        const __half* __restrict__ B2,
        const float* __restrict__ bias,
        float* __restrict__ C, __half* __restrict__ C16,
        int Nc, int K, int lda, int ldc, int zoff, int mode, int kchunk) {
    extern __shared__ __half smh[];

    int z = blockIdx.z;
    const __half* Bm;
    int coff, kb, ke;
    size_t rowoff;
    if (kchunk > 0) {
        Bm = B0; coff = 0;
        kb = z * kchunk;
        ke = min(K, kb + kchunk);
        rowoff = (size_t)z * MM;
    } else {
        Bm = (z == 0) ? B0 : ((z == 1) ? B1 : B2);
        coff = z * zoff;
        kb = 0; ke = K;
        rowoff = 0;
    }

    int tid = threadIdx.x;
    int bn = blockIdx.x * 128, bm = blockIdx.y * 128;
    int warp = tid >> 5, lane = tid & 31;
    int wm = warp >> 2, wn = warp & 3;          // 2 x 4 warp grid, warp tile 64x32
    int g = lane >> 2, tig = lane & 3;

    int lrow = lane & 15;
    int koff8 = (lane & 16) ? 8 : 0;

    uint32_t sbase = smem_u32(smh);

    float acc[4][4][4];
#pragma unroll
    for (int mt = 0; mt < 4; mt++)
#pragma unroll
        for (int nt = 0; nt < 4; nt++)
#pragma unroll
            for (int j = 0; j < 4; j++) acc[mt][nt][j] = 0.f;

    const int NS = (ke - kb + BKK - 1) / BKK;

    // prologue: stages 0..2 in flight
#pragma unroll
    for (int s = 0; s < 3; s++) {
        if (s < NS)
            load_slab_h(A, Bm, Nc, lda, ke, bm, bn, kb + s * BKK,
                        sbase + (uint32_t)(s * STG_H) * 2,
                        sbase + (uint32_t)(s * STG_H + 128 * ASTH) * 2, tid);
        asm volatile("cp.async.commit_group;" ::: "memory");
    }
    asm volatile("cp.async.wait_group 2;" ::: "memory");   // stage 0 ready
    __syncthreads();

    int cst = 0, lst = 3;

    for (int ksl = 0; ksl < NS; ksl++) {
        uint32_t sA = sbase + (uint32_t)(cst * STG_H) * 2;
        uint32_t sB = sA + (uint32_t)(128 * ASTH) * 2;
        uint32_t aw = sA + (uint32_t)((wm * 64 + lrow) * ASTH + koff8) * 2;
        uint32_t bw = sB + (uint32_t)((wn * 32 + lrow) * ASTH + koff8) * 2;

        // compute this slab: 2 k-slices of 16
#pragma unroll
        for (int ks = 0; ks < 2; ks++) {
            uint32_t kb2 = (uint32_t)(ks * 16) * 2;
            uint32_t a[4][4];
#pragma unroll
            for (int mt = 0; mt < 4; mt++)
                ldsm4(a[mt], aw + (uint32_t)(mt * 16 * ASTH) * 2 + kb2);
            uint32_t bfr[2][4];                 // [n-pair][regs]
#pragma unroll
            for (int p = 0; p < 2; p++)
                ldsm4(bfr[p], bw + (uint32_t)(p * 16 * ASTH) * 2 + kb2);
            // bfr[p]: r0=b0(nt=2p), r1=b0(nt=2p+1), r2=b1(nt=2p), r3=b1(nt=2p+1)
#pragma unroll
            for (int mt = 0; mt < 4; mt++) {
#pragma unroll
                for (int nt = 0; nt < 4; nt++) {
                    uint32_t bb[2] = { bfr[nt >> 1][nt & 1], bfr[nt >> 1][2 + (nt & 1)] };
                    mma_f16(acc[mt][nt], a[mt], bb);
                }
            }
        }

        // issue loads for slab ksl+3 (buffer consumed at ksl-1; barrier-separated)
        if (ksl + 3 < NS)
            load_slab_h(A, Bm, Nc, lda, ke, bm, bn, kb + (ksl + 3) * BKK,
                        sbase + (uint32_t)(lst * STG_H) * 2,
                        sbase + (uint32_t)(lst * STG_H + 128 * ASTH) * 2, tid);
        asm volatile("cp.async.commit_group;" ::: "memory");
        asm volatile("cp.async.wait_group 2;" ::: "memory");  // stage ksl+1 ready
        __syncthreads();

        cst = (cst + 1) & 3;
        lst = (lst + 1) & 3;
    }

    // epilogue
    bool fullN = (bn + 128) <= Nc;
#pragma unroll
    for (int mt = 0; mt < 4; mt++) {
        size_t r0 = rowoff + bm + wm * 64 + mt * 16 + g;
        size_t r1 = r0 + 8;
#pragma unroll
        for (int nt = 0; nt < 4; nt++) {
            int lcol = bn + wn * 32 + nt * 8 + 2 * tig;
            int col = coff + lcol;
            float v0 = acc[mt][nt][0], v1 = acc[mt][nt][1];
            float v2 = acc[mt][nt][2], v3 = acc[mt][nt][3];
            if (fullN) {
                if (mode == 1 || mode == 2) {
                    float2 bb = *(const float2*)(bias + lcol);
                    v0 += bb.x; v1 += bb.y; v2 += bb.x; v3 += bb.y;
                }
                if (mode == 2) {
                    __half2 h0 = __halves2half2(__float2half_rn(fmaxf(v0, 0.f)),
                                                __float2half_rn(fmaxf(v1, 0.f)));
                    __half2 h1 = __halves2half2(__float2half_rn(fmaxf(v2, 0.f)),
                                                __float2half_rn(fmaxf(v3, 0.f)));
                    *(__half2*)(C16 + r0 * ldc + col) = h0;
                    *(__half2*)(C16 + r1 * ldc + col) = h1;
                } else {
                    *(float2*)(C + r0 * ldc + col) = make_float2(v0, v1);
                    *(float2*)(C + r1 * ldc + col) = make_float2(v2, v3);
                }
            } else {
                float vv[4] = {v0, v1, v2, v3};
                size_t rr[4] = {r0, r0, r1, r1};
                int cc[4] = {lcol, lcol + 1, lcol, lcol + 1};
#pragma unroll
                for (int j = 0; j < 4; j++) {
                    if (cc[j] >= Nc) continue;
                    float v = vv[j];
                    if (mode == 1 || mode == 2) v += bias[cc[j]];
                    if (mode == 2)
                        C16[rr[j] * ldc + coff + cc[j]] = __float2half_rn(fmaxf(v, 0.f));
                    else
                        C[rr[j] * ldc + coff + cc[j]] = v;
                }
            }
        }
    }
}

// ---------------- attention (qkv f32 packed [MM,3360]) -> att16 fp16 ----------------
__global__ void __launch_bounds__(128)
attn_k(const float* __restrict__ qkv, __half* __restrict__ att) {
    __shared__ float ks[TT][HS + 1];
    __shared__ float vs[TT][HS + 1];

    int bh = blockIdx.x;
    int b = bh / NH, h = bh % NH;
    int t = threadIdx.x;
    const size_t rbase = (size_t)b * TT * QKVN;
    const int hoff = h * HS;

    for (int idx = t; idx < TT * HS; idx += 128) {
        int s = idx / HS, d = idx % HS;
        ks[s][d] = qkv[rbase + (size_t)s * QKVN + HH + hoff + d];
        vs[s][d] = qkv[rbase + (size_t)s * QKVN + 2 * HH + hoff + d];
    }
    __syncthreads();

    float qreg[HS];
#pragma unroll
    for (int d = 0; d < HS; d++)
        qreg[d] = qkv[rbase + (size_t)t * QKVN + hoff + d];

    float m = -1e30f, l = 0.f;
    float out[HS];
#pragma unroll
    for (int d = 0; d < HS; d++) out[d] = 0.f;

    for (int s = 0; s <= t; s++) {
        float dot = 0.f;
#pragma unroll
        for (int d = 0; d < HS; d++)
            dot = fmaf(qreg[d], ks[s][d], dot);
        float sc = dot * ATT_SCALE;
        float mn = fmaxf(m, sc);
        float corr = expf(m - mn);
        float p = expf(sc - mn);
        l = l * corr + p;
#pragma unroll
        for (int d = 0; d < HS; d++)
            out[d] = out[d] * corr + p * vs[s][d];
        m = mn;
    }
    float inv = 1.f / l;
    size_t obase = (size_t)(b * TT + t) * HH + hoff;
#pragma unroll
    for (int d = 0; d < HS; d++)
        att[obase + d] = __float2half_rn(out[d] * inv);
}

// ---------------- launcher ----------------
extern "C" void kernel_launch(void* const* d_in, const int* in_sizes, int n_in,
                              void* d_out, int out_size) {
    (void)in_sizes; (void)n_in; (void)out_size;
    const int*   index = (const int*)  d_in[0];
    const float* tok   = (const float*)d_in[1];
    const float* pos   = (const float*)d_in[2];
    const float* wq    = (const float*)d_in[3];
    const float* wk    = (const float*)d_in[4];
    const float* wv    = (const float*)d_in[5];
    const float* wo    = (const float*)d_in[6];
    const float* bo    = (const float*)d_in[7];
    const float* ln1g  = (const float*)d_in[8];
    const float* ln1b  = (const float*)d_in[9];
    const float* ln2g  = (const float*)d_in[10];
    const float* ln2b  = (const float*)d_in[11];
    const float* w1    = (const float*)d_in[12];
    const float* b1    = (const float*)d_in[13];
    const float* w2    = (const float*)d_in[14];
    const float* b2    = (const float*)d_in[15];
    const float* lnfg  = (const float*)d_in[16];
    const float* lnfb  = (const float*)d_in[17];
    const float* wh    = (const float*)d_in[18];
    const float* bh    = (const float*)d_in[19];
    float* out = (float*)d_out;

    float *x, *qkv, *part;
    __half *y16, *att16, *h16, *w16;
    cudaGetSymbolAddress((void**)&x,     g_x);
    cudaGetSymbolAddress((void**)&qkv,   g_qkv);
    cudaGetSymbolAddress((void**)&part,  g_part);
    cudaGetSymbolAddress((void**)&y16,   g_y16);
    cudaGetSymbolAddress((void**)&att16, g_att16);
    cudaGetSymbolAddress((void**)&h16,   g_h16);
    cudaGetSymbolAddress((void**)&w16,   g_w16);

    cudaFuncSetAttribute(hgemm_k, cudaFuncAttributeMaxDynamicSharedMemorySize, DSMEM);

    dim3 tb(32, 8);

    detect_k<<<1, 256>>>(index);

    // ---- convert all weights: f32 [K][N] -> fp16 [N][KPad], once per launch ----
    convT_k<<<dim3(35, 36, NL), tb>>>(wq, w16 + OFF_QKV,            EDIM, HH, KP,
                                      (size_t)EDIM * HH, (size_t)3 * SZQ);
    convT_k<<<dim3(35, 36, NL), tb>>>(wk, w16 + OFF_QKV + SZQ,      EDIM, HH, KP,
                                      (size_t)EDIM * HH, (size_t)3 * SZQ);
    convT_k<<<dim3(35, 36, NL), tb>>>(wv, w16 + OFF_QKV + 2 * SZQ,  EDIM, HH, KP,
                                      (size_t)EDIM * HH, (size_t)3 * SZQ);
    convT_k<<<dim3(36, 35, NL), tb>>>(wo, w16 + OFF_WO,             HH, EDIM, HH,
                                      (size_t)HH * EDIM, (size_t)SZWO);
    convT_k<<<dim3(143, 36, NL), tb>>>(w1, w16 + OFF_W1,            EDIM, FF, KP,
                                      (size_t)EDIM * FF, (size_t)SZW1);
    convT_k<<<dim3(36, 143, NL), tb>>>(w2, w16 + OFF_W2,            FF, EDIM, FF,
                                      (size_t)FF * EDIM, (size_t)SZW2);
    convT_k<<<dim3(1407, 36, 1), tb>>>(wh, w16 + OFF_WH,            EDIM, VOC, KP,
                                      0, 0);

    embed_ln_k<<<MM, 256>>>(index, tok, pos, ln1g, ln1b, x, y16);

    for (int l = 0; l < NL; l++) {
        const __half* pq  = w16 + OFF_QKV + (size_t)l * 3 * SZQ;
        const __half* pk  = pq + SZQ;
        const __half* pv  = pq + 2 * SZQ;
        const __half* po  = w16 + OFF_WO + (size_t)l * SZWO;
        const __half* p1  = w16 + OFF_W1 + (size_t)l * SZW1;
        const __half* p2  = w16 + OFF_W2 + (size_t)l * SZW2;
        const float* pbo = bo + (size_t)l * EDIM;
        const float* g2  = ln2g + (size_t)l * EDIM;
        const float* be2 = ln2b + (size_t)l * EDIM;
        const float* pb1 = b1 + (size_t)l * FF;
        const float* pb2 = b2 + (size_t)l * EDIM;
        const float* gn  = (l + 1 < NL) ? ln1g + (size_t)(l + 1) * EDIM : lnfg;
        const float* bn_ = (l + 1 < NL) ? ln1b + (size_t)(l + 1) * EDIM : lnfb;

        // QKV fused (z selects weight), f32 out into packed qkv
        hgemm_k<<<dim3(9, 8, 3), 256, DSMEM>>>(
            y16, pq, pk, pv, nullptr, qkv, nullptr, HH, KP, KP, QKVN, HH, 0, 0);

        attn_k<<<BB * NH, 128>>>(qkv, att16);

        // wo: split-K x4 partials, then fused reduce+bias+residual+LN2
        hgemm_k<<<dim3(9, 8, 4), 256, DSMEM>>>(
            att16, po, nullptr, nullptr, nullptr, part, nullptr,
            EDIM, HH, HH, EDIM, 0, 4, 280);
        reduce4ln_k<<<MM, 256>>>(part, pbo, x, g2, be2, y16);

        // w1: relu(y @ w1 + b1) -> fp16 h
        hgemm_k<<<dim3(36, 8, 1), 256, DSMEM>>>(
            y16, p1, nullptr, nullptr, pb1, nullptr, h16, FF, KP, KP, FF, 0, 2, 0);

        // w2: split-K x4 partials, then fused reduce+bias+residual+LN (next ln1 / lnf)
        hgemm_k<<<dim3(9, 8, 4), 256, DSMEM>>>(
            h16, p2, nullptr, nullptr, nullptr, part, nullptr,
            EDIM, FF, FF, EDIM, 0, 4, 1152);
        reduce4ln_k<<<MM, 256>>>(part, pb2, x, gn, bn_, y16);
    }

    // head: logits = lnf(x) @ wh + bh
    hgemm_k<<<dim3(352, 8, 1), 256, DSMEM>>>(
        y16, w16 + OFF_WH, nullptr, nullptr, bh, out, nullptr,
        VOC, KP, KP, VOC, 0, 1, 0);
}

// round 8
// speedup vs baseline: 8.3680x; 1.0655x over previous
#include <cuda_runtime.h>
#include <cuda_fp16.h>
#include <cstdint>
#include <math.h>

// ---------------- problem constants ----------------
#define EDIM 1140
#define KP   1144            // EDIM padded to mult of 8 (fp16 16B chunks)
#define HH   1120
#define NH   32
#define HS   35
#define NL   36
#define VOC  45000
#define TT   128
#define BB   8
#define MM   1024
#define FF   4560
#define QKVN 3360
#define ATT_SCALE 0.16903085094570331f

// ---------------- converted-weight layout (fp16, transposed [N][K]) ----------------
#define SZQ  (1120*KP)
#define OFF_QKV ((size_t)0)
#define SZWO (1140*1120)
#define OFF_WO  ((size_t)NL*3*SZQ)
#define SZW1 (4560*KP)
#define OFF_W1  (OFF_WO + (size_t)NL*SZWO)
#define SZW2 (1140*4560)
#define OFF_W2  (OFF_W1 + (size_t)NL*SZW1)
#define OFF_WH  (OFF_W2 + (size_t)NL*SZW2)
#define WTOT    (OFF_WH + (size_t)VOC*KP)

// ---------------- scratch (device globals) ----------------
__device__ float  g_x[MM * EDIM];
__device__ float  g_qkv[MM * QKVN];
__device__ float  g_part[4 * MM * EDIM];
__device__ __half g_y16[MM * KP];
__device__ __half g_att16[MM * HH];
__device__ __half g_h16[MM * FF];
__device__ __half g_w16[WTOT];
__device__ int    g_is64;

// ---------------- helpers ----------------
__device__ __forceinline__ uint32_t smem_u32(const void* p) {
    uint32_t a;
    asm("{ .reg .u64 t; cvta.to.shared.u64 t, %1; cvt.u32.u64 %0, t; }" : "=r"(a) : "l"(p));
    return a;
}
__device__ __forceinline__ void cpa16(uint32_t s, const void* g) {
    asm volatile("cp.async.cg.shared.global [%0], [%1], 16;" :: "r"(s), "l"(g) : "memory");
}
__device__ __forceinline__ void zfill16(uint32_t s) {
    asm volatile("st.shared.v4.b32 [%0], {%1,%1,%1,%1};" :: "r"(s), "r"(0) : "memory");
}
__device__ __forceinline__ void mma_f16(float* d, const uint32_t* a, const uint32_t* b) {
    asm volatile(
        "mma.sync.aligned.m16n8k16.row.col.f32.f16.f16.f32 "
        "{%0,%1,%2,%3}, {%4,%5,%6,%7}, {%8,%9}, {%0,%1,%2,%3};"
        : "+f"(d[0]), "+f"(d[1]), "+f"(d[2]), "+f"(d[3])
        : "r"(a[0]), "r"(a[1]), "r"(a[2]), "r"(a[3]), "r"(b[0]), "r"(b[1]));
}
__device__ __forceinline__ void ldsm4(uint32_t* r, uint32_t a) {
    asm volatile("ldmatrix.sync.aligned.m8n8.x4.shared.b16 {%0,%1,%2,%3}, [%4];"
        : "=r"(r[0]), "=r"(r[1]), "=r"(r[2]), "=r"(r[3]) : "r"(a));
}

// ---------------- index dtype detection ----------------
__global__ void detect_k(const int* __restrict__ raw) {
    __shared__ int any;
    if (threadIdx.x == 0) any = 0;
    __syncthreads();
    int local = 0;
    for (int i = threadIdx.x; i < 512; i += blockDim.x)
        if (raw[2 * i + 1] != 0) local = 1;
    if (local) atomicOr(&any, 1);
    __syncthreads();
    if (threadIdx.x == 0) g_is64 = any ? 0 : 1;
}

// ---------------- weight convert: f32 [K][N] -> fp16 [N][KPad] (RN), zero K-pad ----------------
__global__ void convT_k(const float* __restrict__ in, __half* __restrict__ out,
                        int K, int N, int KPad, size_t inLs, size_t outLs) {
    in  += (size_t)blockIdx.z * inLs;
    out += (size_t)blockIdx.z * outLs;
    __shared__ float t[32][33];
    int bn = blockIdx.x * 32, bk = blockIdx.y * 32;
    int x = threadIdx.x, y = threadIdx.y;
#pragma unroll
    for (int i = 0; i < 32; i += 8) {
        int k = bk + y + i, n = bn + x;
        t[y + i][x] = (k < K && n < N) ? in[(size_t)k * N + n] : 0.f;
    }
    __syncthreads();
#pragma unroll
    for (int i = 0; i < 32; i += 8) {
        int n = bn + y + i, k = bk + x;
        if (n < N && k < KPad) out[(size_t)n * KPad + k] = __float2half_rn(t[x][y + i]);
    }
}

// ---------------- block row-LN from smem values -> y16 (fp16, zero-padded to KP) ----------------
__device__ __forceinline__ void row_ln_emit(const float* v, float s, float s2,
                                            const float* g, const float* b,
                                            __half* yrow) {
    __shared__ float sh0[8], sh1[8];
    for (int o = 16; o > 0; o >>= 1) {
        s  += __shfl_down_sync(0xffffffffu, s, o);
        s2 += __shfl_down_sync(0xffffffffu, s2, o);
    }
    int w = threadIdx.x >> 5, lane = threadIdx.x & 31;
    if (lane == 0) { sh0[w] = s; sh1[w] = s2; }
    __syncthreads();
    if (threadIdx.x == 0) {
        float ts = 0.f, ts2 = 0.f;
        for (int i = 0; i < 8; i++) { ts += sh0[i]; ts2 += sh1[i]; }
        float mu = ts / (float)EDIM;
        float var = ts2 / (float)EDIM - mu * mu;
        sh0[0] = mu;
        sh1[0] = rsqrtf(var + 1e-5f);
    }
    __syncthreads();
    float mu = sh0[0], rstd = sh1[0];
    for (int c = threadIdx.x; c < KP; c += blockDim.x) {
        float o = (c < EDIM) ? (v[c] - mu) * rstd * g[c] + b[c] : 0.f;
        yrow[c] = __float2half_rn(o);
    }
}

// ---------------- embedding + LN1(layer0) ----------------
__global__ void embed_ln_k(const int* __restrict__ raw,
                           const float* __restrict__ tok,
                           const float* __restrict__ pos,
                           const float* __restrict__ g,
                           const float* __restrict__ b,
                           float* __restrict__ x, __half* __restrict__ y16) {
    __shared__ float v[EDIM];
    int r = blockIdx.x, t = r % TT;
    int idx = g_is64 ? raw[2 * r] : raw[r];
    const float* te = tok + (size_t)idx * EDIM;
    const float* pe = pos + (size_t)t * EDIM;
    float s = 0.f, s2 = 0.f;
    for (int c = threadIdx.x; c < EDIM; c += blockDim.x) {
        float val = te[c] + pe[c];
        v[c] = val;
        x[(size_t)r * EDIM + c] = val;
        s += val; s2 = fmaf(val, val, s2);
    }
    __syncthreads();
    row_ln_emit(v, s, s2, g, b, y16 + (size_t)r * KP);
}

// ---------------- split-K reduce + residual + bias -> x; then LN -> y16 ----------------
__global__ void reduce4ln_k(const float* __restrict__ part,
                            const float* __restrict__ bias,
                            float* __restrict__ x,
                            const float* __restrict__ g,
                            const float* __restrict__ b,
                            __half* __restrict__ y16) {
    __shared__ float v[EDIM];
    int r = blockIdx.x;
    const float* p0 = part + (size_t)r * EDIM;
    const float* p1 = p0 + (size_t)MM * EDIM;
    const float* p2 = p1 + (size_t)MM * EDIM;
    const float* p3 = p2 + (size_t)MM * EDIM;
    float* xr = x + (size_t)r * EDIM;
    float s = 0.f, s2 = 0.f;
    for (int c = threadIdx.x; c < EDIM; c += blockDim.x) {
        float val = ((p0[c] + p1[c]) + (p2[c] + p3[c])) + bias[c] + xr[c];
        xr[c] = val;
        v[c] = val;
        s += val; s2 = fmaf(val, val, s2);
    }
    __syncthreads();
    row_ln_emit(v, s, s2, g, b, y16 + (size_t)r * KP);
}

// ---------------- fp16 tensor-core GEMM (BKK=64, 3-stage) ----------------
// C[1024, Nc] = A16[1024, K] @ B16t[Nc, K]^T  (both fp16, K-contiguous, lda = padded K)
// kchunk==0: blockIdx.z selects B0/B1/B2, output col offset z*zoff (fused QKV)
// kchunk>0 : blockIdx.z = split-K index, partial f32 at C[(z*MM+row)*ldc+col]
// mode 0: plain f32  1: +bias f32  2: relu(+bias) -> fp16 C16  4: raw partial f32
#define BKK 64
#define ASTH 72                         // smem pitch in halfs (144 B, ldsm conflict-free)
#define STG_H (2 * 128 * ASTH)          // A + B halfs per stage = 18432
#define NSTG 3
#define DSMEM (NSTG * STG_H * 2)        // 110592 B -> 2 CTAs/SM = 221 KB

__device__ __forceinline__ void load_slab_h(const __half* __restrict__ A,
                                            const __half* __restrict__ B,
                                            int Nc, int lda, int kend,
                                            int bm, int bn, int k0,
                                            uint32_t sA, uint32_t sB, int tid) {
#pragma unroll
    for (int i = 0; i < 4; i++) {                  // A: 128 rows x 64 k
        int c = tid + i * 256;
        int row = c >> 3;
        int kc = (c & 7) * 8;
        int gk = k0 + kc;
        uint32_t off = sA + (uint32_t)(row * ASTH + kc) * 2;
        if (gk < kend) cpa16(off, A + (size_t)(bm + row) * lda + gk);
        else           zfill16(off);
    }
#pragma unroll
    for (int i = 0; i < 4; i++) {                  // B: 128 n-rows x 64 k
        int c = tid + i * 256;
        int row = c >> 3;
        int kc = (c & 7) * 8;
        int gk = k0 + kc;
        uint32_t off = sB + (uint32_t)(row * ASTH + kc) * 2;
        if (gk < kend && (bn + row) < Nc) cpa16(off, B + (size_t)(bn + row) * lda + gk);
        else                              zfill16(off);
    }
}

__global__ void __launch_bounds__(256, 2)
hgemm_k(const __half* __restrict__ A,
        const __half* __restrict__ B0, const __half* __restrict__ B1,
        const __half* __restrict__ B2,
        const float* __restrict__ bias,
        float* __restrict__ C, __half* __restrict__ C16,
        int Nc, int K, int lda, int ldc, int zoff, int mode, int kchunk) {
    extern __shared__ __half smh[];

    int z = blockIdx.z;
    const __half* Bm;
    int coff, kb, ke;
    size_t rowoff;
    if (kchunk > 0) {
        Bm = B0; coff = 0;
        kb = z * kchunk;
        ke = min(K, kb + kchunk);
        rowoff = (size_t)z * MM;
    } else {
        Bm = (z == 0) ? B0 : ((z == 1) ? B1 : B2);
        coff = z * zoff;
        kb = 0; ke = K;
        rowoff = 0;
    }

    int tid = threadIdx.x;
    int bn = blockIdx.x * 128, bm = blockIdx.y * 128;
    int warp = tid >> 5, lane = tid & 31;
    int wm = warp >> 2, wn = warp & 3;          // 2 x 4 warp grid, warp tile 64x32
    int g = lane >> 2, tig = lane & 3;

    int lrow = lane & 15;
    int koff8 = (lane & 16) ? 8 : 0;

    uint32_t sbase = smem_u32(smh);

    float acc[4][4][4];
#pragma unroll
    for (int mt = 0; mt < 4; mt++)
#pragma unroll
        for (int nt = 0; nt < 4; nt++)
#pragma unroll
            for (int j = 0; j < 4; j++) acc[mt][nt][j] = 0.f;

    const int NS = (ke - kb + BKK - 1) / BKK;

    // prologue: stages 0,1 in flight
#pragma unroll
    for (int s = 0; s < 2; s++) {
        if (s < NS)
            load_slab_h(A, Bm, Nc, lda, ke, bm, bn, kb + s * BKK,
                        sbase + (uint32_t)(s * STG_H) * 2,
                        sbase + (uint32_t)(s * STG_H + 128 * ASTH) * 2, tid);
        asm volatile("cp.async.commit_group;" ::: "memory");
    }
    asm volatile("cp.async.wait_group 1;" ::: "memory");   // stage 0 ready
    __syncthreads();

    int cst = 0, lst = 2;

    for (int ksl = 0; ksl < NS; ksl++) {
        uint32_t sA = sbase + (uint32_t)(cst * STG_H) * 2;
        uint32_t sB = sA + (uint32_t)(128 * ASTH) * 2;
        uint32_t aw = sA + (uint32_t)((wm * 64 + lrow) * ASTH + koff8) * 2;
        uint32_t bw = sB + (uint32_t)((wn * 32 + lrow) * ASTH + koff8) * 2;

        // compute this slab: 4 k-slices of 16
#pragma unroll
        for (int ks = 0; ks < 4; ks++) {
            uint32_t kb2 = (uint32_t)(ks * 16) * 2;
            uint32_t a[4][4];
#pragma unroll
            for (int mt = 0; mt < 4; mt++)
                ldsm4(a[mt], aw + (uint32_t)(mt * 16 * ASTH) * 2 + kb2);
            uint32_t bfr[2][4];
#pragma unroll
            for (int p = 0; p < 2; p++)
                ldsm4(bfr[p], bw + (uint32_t)(p * 16 * ASTH) * 2 + kb2);
#pragma unroll
            for (int mt = 0; mt < 4; mt++) {
#pragma unroll
                for (int nt = 0; nt < 4; nt++) {
                    uint32_t bb[2] = { bfr[nt >> 1][nt & 1], bfr[nt >> 1][2 + (nt & 1)] };
                    mma_f16(acc[mt][nt], a[mt], bb);
                }
            }
        }

        // issue loads for slab ksl+2 (buffer consumed at ksl-1; barrier-separated)
        if (ksl + 2 < NS)
            load_slab_h(A, Bm, Nc, lda, ke, bm, bn, kb + (ksl + 2) * BKK,
                        sbase + (uint32_t)(lst * STG_H) * 2,
                        sbase + (uint32_t)(lst * STG_H + 128 * ASTH) * 2, tid);
        asm volatile("cp.async.commit_group;" ::: "memory");
        asm volatile("cp.async.wait_group 1;" ::: "memory");  // stage ksl+1 ready
        __syncthreads();

        if (++cst == NSTG) cst = 0;
        if (++lst == NSTG) lst = 0;
    }

    // epilogue
    bool fullN = (bn + 128) <= Nc;
#pragma unroll
    for (int mt = 0; mt < 4; mt++) {
        size_t r0 = rowoff + bm + wm * 64 + mt * 16 + g;
        size_t r1 = r0 + 8;
#pragma unroll
        for (int nt = 0; nt < 4; nt++) {
            int lcol = bn + wn * 32 + nt * 8 + 2 * tig;
            int col = coff + lcol;
            float v0 = acc[mt][nt][0], v1 = acc[mt][nt][1];
            float v2 = acc[mt][nt][2], v3 = acc[mt][nt][3];
            if (fullN) {
                if (mode == 1 || mode == 2) {
                    float2 bb = *(const float2*)(bias + lcol);
                    v0 += bb.x; v1 += bb.y; v2 += bb.x; v3 += bb.y;
                }
                if (mode == 2) {
                    __half2 h0 = __halves2half2(__float2half_rn(fmaxf(v0, 0.f)),
                                                __float2half_rn(fmaxf(v1, 0.f)));
                    __half2 h1 = __halves2half2(__float2half_rn(fmaxf(v2, 0.f)),
                                                __float2half_rn(fmaxf(v3, 0.f)));
                    *(__half2*)(C16 + r0 * ldc + col) = h0;
                    *(__half2*)(C16 + r1 * ldc + col) = h1;
                } else {
                    *(float2*)(C + r0 * ldc + col) = make_float2(v0, v1);
                    *(float2*)(C + r1 * ldc + col) = make_float2(v2, v3);
                }
            } else {
                float vv[4] = {v0, v1, v2, v3};
                size_t rr[4] = {r0, r0, r1, r1};
                int cc[4] = {lcol, lcol + 1, lcol, lcol + 1};
#pragma unroll
                for (int j = 0; j < 4; j++) {
                    if (cc[j] >= Nc) continue;
                    float v = vv[j];
                    if (mode == 1 || mode == 2) v += bias[cc[j]];
                    if (mode == 2)
                        C16[rr[j] * ldc + coff + cc[j]] = __float2half_rn(fmaxf(v, 0.f));
                    else
                        C[rr[j] * ldc + coff + cc[j]] = v;
                }
            }
        }
    }
}

// ---------------- attention (qkv f32 packed [MM,3360]) -> att16 fp16 ----------------
__global__ void __launch_bounds__(128)
attn_k(const float* __restrict__ qkv, __half* __restrict__ att) {
    __shared__ float ks[TT][HS + 1];
    __shared__ float vs[TT][HS + 1];

    int bh = blockIdx.x;
    int b = bh / NH, h = bh % NH;
    int t = threadIdx.x;
    const size_t rbase = (size_t)b * TT * QKVN;
    const int hoff = h * HS;

    for (int idx = t; idx < TT * HS; idx += 128) {
        int s = idx / HS, d = idx % HS;
        ks[s][d] = qkv[rbase + (size_t)s * QKVN + HH + hoff + d];
        vs[s][d] = qkv[rbase + (size_t)s * QKVN + 2 * HH + hoff + d];
    }
    __syncthreads();

    float qreg[HS];
#pragma unroll
    for (int d = 0; d < HS; d++)
        qreg[d] = qkv[rbase + (size_t)t * QKVN + hoff + d];

    float m = -1e30f, l = 0.f;
    float out[HS];
#pragma unroll
    for (int d = 0; d < HS; d++) out[d] = 0.f;

    for (int s = 0; s <= t; s++) {
        float dot = 0.f;
#pragma unroll
        for (int d = 0; d < HS; d++)
            dot = fmaf(qreg[d], ks[s][d], dot);
        float sc = dot * ATT_SCALE;
        float mn = fmaxf(m, sc);
        float corr = expf(m - mn);
        float p = expf(sc - mn);
        l = l * corr + p;
#pragma unroll
        for (int d = 0; d < HS; d++)
            out[d] = out[d] * corr + p * vs[s][d];
        m = mn;
    }
    float inv = 1.f / l;
    size_t obase = (size_t)(b * TT + t) * HH + hoff;
#pragma unroll
    for (int d = 0; d < HS; d++)
        att[obase + d] = __float2half_rn(out[d] * inv);
}

// ---------------- launcher ----------------
extern "C" void kernel_launch(void* const* d_in, const int* in_sizes, int n_in,
                              void* d_out, int out_size) {
    (void)in_sizes; (void)n_in; (void)out_size;
    const int*   index = (const int*)  d_in[0];
    const float* tok   = (const float*)d_in[1];
    const float* pos   = (const float*)d_in[2];
    const float* wq    = (const float*)d_in[3];
    const float* wk    = (const float*)d_in[4];
    const float* wv    = (const float*)d_in[5];
    const float* wo    = (const float*)d_in[6];
    const float* bo    = (const float*)d_in[7];
    const float* ln1g  = (const float*)d_in[8];
    const float* ln1b  = (const float*)d_in[9];
    const float* ln2g  = (const float*)d_in[10];
    const float* ln2b  = (const float*)d_in[11];
    const float* w1    = (const float*)d_in[12];
    const float* b1    = (const float*)d_in[13];
    const float* w2    = (const float*)d_in[14];
    const float* b2    = (const float*)d_in[15];
    const float* lnfg  = (const float*)d_in[16];
    const float* lnfb  = (const float*)d_in[17];
    const float* wh    = (const float*)d_in[18];
    const float* bh    = (const float*)d_in[19];
    float* out = (float*)d_out;

    float *x, *qkv, *part;
    __half *y16, *att16, *h16, *w16;
    cudaGetSymbolAddress((void**)&x,     g_x);
    cudaGetSymbolAddress((void**)&qkv,   g_qkv);
    cudaGetSymbolAddress((void**)&part,  g_part);
    cudaGetSymbolAddress((void**)&y16,   g_y16);
    cudaGetSymbolAddress((void**)&att16, g_att16);
    cudaGetSymbolAddress((void**)&h16,   g_h16);
    cudaGetSymbolAddress((void**)&w16,   g_w16);

    cudaFuncSetAttribute(hgemm_k, cudaFuncAttributeMaxDynamicSharedMemorySize, DSMEM);

    dim3 tb(32, 8);

    detect_k<<<1, 256>>>(index);

    // ---- convert all weights: f32 [K][N] -> fp16 [N][KPad], once per launch ----
    convT_k<<<dim3(35, 36, NL), tb>>>(wq, w16 + OFF_QKV,            EDIM, HH, KP,
                                      (size_t)EDIM * HH, (size_t)3 * SZQ);
    convT_k<<<dim3(35, 36, NL), tb>>>(wk, w16 + OFF_QKV + SZQ,      EDIM, HH, KP,
                                      (size_t)EDIM * HH, (size_t)3 * SZQ);
    convT_k<<<dim3(35, 36, NL), tb>>>(wv, w16 + OFF_QKV + 2 * SZQ,  EDIM, HH, KP,
                                      (size_t)EDIM * HH, (size_t)3 * SZQ);
    convT_k<<<dim3(36, 35, NL), tb>>>(wo, w16 + OFF_WO,             HH, EDIM, HH,
                                      (size_t)HH * EDIM, (size_t)SZWO);
    convT_k<<<dim3(143, 36, NL), tb>>>(w1, w16 + OFF_W1,            EDIM, FF, KP,
                                      (size_t)EDIM * FF, (size_t)SZW1);
    convT_k<<<dim3(36, 143, NL), tb>>>(w2, w16 + OFF_W2,            FF, EDIM, FF,
                                      (size_t)FF * EDIM, (size_t)SZW2);
    convT_k<<<dim3(1407, 36, 1), tb>>>(wh, w16 + OFF_WH,            EDIM, VOC, KP,
                                      0, 0);

    embed_ln_k<<<MM, 256>>>(index, tok, pos, ln1g, ln1b, x, y16);

    for (int l = 0; l < NL; l++) {
        const __half* pq  = w16 + OFF_QKV + (size_t)l * 3 * SZQ;
        const __half* pk  = pq + SZQ;
        const __half* pv  = pq + 2 * SZQ;
        const __half* po  = w16 + OFF_WO + (size_t)l * SZWO;
        const __half* p1  = w16 + OFF_W1 + (size_t)l * SZW1;
        const __half* p2  = w16 + OFF_W2 + (size_t)l * SZW2;
        const float* pbo = bo + (size_t)l * EDIM;
        const float* g2  = ln2g + (size_t)l * EDIM;
        const float* be2 = ln2b + (size_t)l * EDIM;
        const float* pb1 = b1 + (size_t)l * FF;
        const float* pb2 = b2 + (size_t)l * EDIM;
        const float* gn  = (l + 1 < NL) ? ln1g + (size_t)(l + 1) * EDIM : lnfg;
        const float* bn_ = (l + 1 < NL) ? ln1b + (size_t)(l + 1) * EDIM : lnfb;

        // QKV fused (z selects weight), f32 out into packed qkv
        hgemm_k<<<dim3(9, 8, 3), 256, DSMEM>>>(
            y16, pq, pk, pv, nullptr, qkv, nullptr, HH, KP, KP, QKVN, HH, 0, 0);

        attn_k<<<BB * NH, 128>>>(qkv, att16);

        // wo: split-K x4 partials, then fused reduce+bias+residual+LN2
        hgemm_k<<<dim3(9, 8, 4), 256, DSMEM>>>(
            att16, po, nullptr, nullptr, nullptr, part, nullptr,
            EDIM, HH, HH, EDIM, 0, 4, 280);
        reduce4ln_k<<<MM, 256>>>(part, pbo, x, g2, be2, y16);

        // w1: relu(y @ w1 + b1) -> fp16 h
        hgemm_k<<<dim3(36, 8, 1), 256, DSMEM>>>(
            y16, p1, nullptr, nullptr, pb1, nullptr, h16, FF, KP, KP, FF, 0, 2, 0);

        // w2: split-K x4 partials, then fused reduce+bias+residual+LN (next ln1 / lnf)
        hgemm_k<<<dim3(9, 8, 4), 256, DSMEM>>>(
            h16, p2, nullptr, nullptr, nullptr, part, nullptr,
            EDIM, FF, FF, EDIM, 0, 4, 1152);
        reduce4ln_k<<<MM, 256>>>(part, pb2, x, gn, bn_, y16);
    }

    // head: logits = lnf(x) @ wh + bh
    hgemm_k<<<dim3(352, 8, 1), 256, DSMEM>>>(
        y16, w16 + OFF_WH, nullptr, nullptr, bh, out, nullptr,
        VOC, KP, KP, VOC, 0, 1, 0);
}

// round 9
// speedup vs baseline: 8.6848x; 1.0379x over previous
#include <cuda_runtime.h>
#include <cuda_fp16.h>
#include <cstdint>
#include <math.h>

// ---------------- problem constants ----------------
#define EDIM 1140
#define KP   1144            // EDIM padded to mult of 8 (fp16 16B chunks)
#define HH   1120
#define NH   32
#define HS   35
#define NL   36
#define VOC  45000
#define TT   128
#define BB   8
#define MM   1024
#define FF   4560
#define QKVN 3360
#define ATT_SCALE 0.16903085094570331f

// ---------------- converted-weight layout (fp16, transposed [N][K]) ----------------
#define SZQ  (1120*KP)
#define OFF_QKV ((size_t)0)
#define SZWO (1140*1120)
#define OFF_WO  ((size_t)NL*3*SZQ)
#define SZW1 (4560*KP)
#define OFF_W1  (OFF_WO + (size_t)NL*SZWO)
#define SZW2 (1140*4560)
#define OFF_W2  (OFF_W1 + (size_t)NL*SZW1)
#define OFF_WH  (OFF_W2 + (size_t)NL*SZW2)
#define WTOT    (OFF_WH + (size_t)VOC*KP)

// ---------------- scratch (device globals) ----------------
__device__ float  g_x[MM * EDIM];
__device__ float  g_qkv[MM * QKVN];
__device__ float  g_part[4 * MM * EDIM];
__device__ __half g_y16[MM * KP];
__device__ __half g_att16[MM * HH];
__device__ __half g_h16[MM * FF];
__device__ __half g_w16[WTOT];
__device__ int    g_is64;

// ---------------- helpers ----------------
__device__ __forceinline__ uint32_t smem_u32(const void* p) {
    uint32_t a;
    asm("{ .reg .u64 t; cvta.to.shared.u64 t, %1; cvt.u32.u64 %0, t; }" : "=r"(a) : "l"(p));
    return a;
}
__device__ __forceinline__ void cpa16(uint32_t s, const void* g) {
    asm volatile("cp.async.cg.shared.global [%0], [%1], 16;" :: "r"(s), "l"(g) : "memory");
}
__device__ __forceinline__ void zfill16(uint32_t s) {
    asm volatile("st.shared.v4.b32 [%0], {%1,%1,%1,%1};" :: "r"(s), "r"(0) : "memory");
}
__device__ __forceinline__ void mma_f16(float* d, const uint32_t* a, const uint32_t* b) {
    asm volatile(
        "mma.sync.aligned.m16n8k16.row.col.f32.f16.f16.f32 "
        "{%0,%1,%2,%3}, {%4,%5,%6,%7}, {%8,%9}, {%0,%1,%2,%3};"
        : "+f"(d[0]), "+f"(d[1]), "+f"(d[2]), "+f"(d[3])
        : "r"(a[0]), "r"(a[1]), "r"(a[2]), "r"(a[3]), "r"(b[0]), "r"(b[1]));
}
__device__ __forceinline__ void ldsm4(uint32_t* r, uint32_t a) {
    asm volatile("ldmatrix.sync.aligned.m8n8.x4.shared.b16 {%0,%1,%2,%3}, [%4];"
        : "=r"(r[0]), "=r"(r[1]), "=r"(r[2]), "=r"(r[3]) : "r"(a));
}
__device__ __forceinline__ void ldsm2(uint32_t* r, uint32_t a) {
    asm volatile("ldmatrix.sync.aligned.m8n8.x2.shared.b16 {%0,%1}, [%2];"
        : "=r"(r[0]), "=r"(r[1]) : "r"(a));
}

// ---------------- index dtype detection ----------------
__global__ void detect_k(const int* __restrict__ raw) {
    __shared__ int any;
    if (threadIdx.x == 0) any = 0;
    __syncthreads();
    int local = 0;
    for (int i = threadIdx.x; i < 512; i += blockDim.x)
        if (raw[2 * i + 1] != 0) local = 1;
    if (local) atomicOr(&any, 1);
    __syncthreads();
    if (threadIdx.x == 0) g_is64 = any ? 0 : 1;
}

// ---------------- weight convert: f32 [K][N] -> fp16 [N][KPad] (RN), zero K-pad ----------
// 64k x 32n tiles; float-wide coalesced reads, __half2 coalesced writes.
__global__ void convT_k(const float* __restrict__ in, __half* __restrict__ out,
                        int K, int N, int KPad, size_t inLs, size_t outLs) {
    in  += (size_t)blockIdx.z * inLs;
    out += (size_t)blockIdx.z * outLs;
    __shared__ float t[64][33];
    int bn = blockIdx.x * 32, bk = blockIdx.y * 64;
    int x = threadIdx.x, y = threadIdx.y;
#pragma unroll
    for (int i = 0; i < 64; i += 8) {
        int k = bk + y + i, n = bn + x;
        t[y + i][x] = (k < K && n < N) ? in[(size_t)k * N + n] : 0.f;
    }
    __syncthreads();
#pragma unroll
    for (int i = 0; i < 32; i += 8) {
        int n = bn + y + i;
        int k = bk + 2 * x;
        if (n < N && k < KPad) {
            __half2 h = __halves2half2(__float2half_rn(t[2 * x][y + i]),
                                       __float2half_rn(t[2 * x + 1][y + i]));
            *(__half2*)(out + (size_t)n * KPad + k) = h;
        }
    }
}

// ---------------- block row-LN from smem values -> y16 (fp16, zero-padded to KP) ----------------
__device__ __forceinline__ void row_ln_emit(const float* v, float s, float s2,
                                            const float* g, const float* b,
                                            __half* yrow) {
    __shared__ float sh0[8], sh1[8];
    for (int o = 16; o > 0; o >>= 1) {
        s  += __shfl_down_sync(0xffffffffu, s, o);
        s2 += __shfl_down_sync(0xffffffffu, s2, o);
    }
    int w = threadIdx.x >> 5, lane = threadIdx.x & 31;
    if (lane == 0) { sh0[w] = s; sh1[w] = s2; }
    __syncthreads();
    if (threadIdx.x == 0) {
        float ts = 0.f, ts2 = 0.f;
        for (int i = 0; i < 8; i++) { ts += sh0[i]; ts2 += sh1[i]; }
        float mu = ts / (float)EDIM;
        float var = ts2 / (float)EDIM - mu * mu;
        sh0[0] = mu;
        sh1[0] = rsqrtf(var + 1e-5f);
    }
    __syncthreads();
    float mu = sh0[0], rstd = sh1[0];
    for (int c = threadIdx.x; c < KP; c += blockDim.x) {
        float o = (c < EDIM) ? (v[c] - mu) * rstd * g[c] + b[c] : 0.f;
        yrow[c] = __float2half_rn(o);
    }
}

// ---------------- embedding + LN1(layer0) ----------------
__global__ void embed_ln_k(const int* __restrict__ raw,
                           const float* __restrict__ tok,
                           const float* __restrict__ pos,
                           const float* __restrict__ g,
                           const float* __restrict__ b,
                           float* __restrict__ x, __half* __restrict__ y16) {
    __shared__ float v[EDIM];
    int r = blockIdx.x, t = r % TT;
    int idx = g_is64 ? raw[2 * r] : raw[r];
    const float* te = tok + (size_t)idx * EDIM;
    const float* pe = pos + (size_t)t * EDIM;
    float s = 0.f, s2 = 0.f;
    for (int c = threadIdx.x; c < EDIM; c += blockDim.x) {
        float val = te[c] + pe[c];
        v[c] = val;
        x[(size_t)r * EDIM + c] = val;
        s += val; s2 = fmaf(val, val, s2);
    }
    __syncthreads();
    row_ln_emit(v, s, s2, g, b, y16 + (size_t)r * KP);
}

// ---------------- split-K reduce + residual + bias -> x; then LN -> y16 (float4) -------------
__global__ void reduce4ln_k(const float* __restrict__ part,
                            const float* __restrict__ bias,
                            float* __restrict__ x,
                            const float* __restrict__ g,
                            const float* __restrict__ b,
                            __half* __restrict__ y16) {
    __shared__ float v[EDIM];
    int r = blockIdx.x;
    const float4* p0 = (const float4*)(part + (size_t)r * EDIM);
    const float4* p1 = (const float4*)(part + (size_t)MM * EDIM + (size_t)r * EDIM);
    const float4* p2 = (const float4*)(part + (size_t)2 * MM * EDIM + (size_t)r * EDIM);
    const float4* p3 = (const float4*)(part + (size_t)3 * MM * EDIM + (size_t)r * EDIM);
    const float4* bb = (const float4*)bias;
    float4* xr = (float4*)(x + (size_t)r * EDIM);
    float s = 0.f, s2 = 0.f;
    for (int c = threadIdx.x; c < EDIM / 4; c += blockDim.x) {
        float4 a0 = p0[c], a1 = p1[c], a2 = p2[c], a3 = p3[c];
        float4 bv = bb[c], xv = xr[c];
        float4 val;
        val.x = ((a0.x + a1.x) + (a2.x + a3.x)) + bv.x + xv.x;
        val.y = ((a0.y + a1.y) + (a2.y + a3.y)) + bv.y + xv.y;
        val.z = ((a0.z + a1.z) + (a2.z + a3.z)) + bv.z + xv.z;
        val.w = ((a0.w + a1.w) + (a2.w + a3.w)) + bv.w + xv.w;
        xr[c] = val;
        *(float4*)(v + 4 * c) = val;
        s += val.x + val.y + val.z + val.w;
        s2 = fmaf(val.x, val.x, s2);
        s2 = fmaf(val.y, val.y, s2);
        s2 = fmaf(val.z, val.z, s2);
        s2 = fmaf(val.w, val.w, s2);
    }
    __syncthreads();
    row_ln_emit(v, s, s2, g, b, y16 + (size_t)r * KP);
}

// ---------------- fp16 tensor-core GEMM (BKK=64, 3-stage), templated on BN ----------------
// C[1024, Nc] = A16[1024, K] @ B16t[Nc, K]^T  (both fp16, K-contiguous, lda = padded K)
// kchunk==0: blockIdx.z selects B0/B1/B2, output col offset z*zoff
// kchunk>0 : blockIdx.z = split-K index, partial f32 at C[(z*MM+row)*ldc+col]
// mode 0: plain f32  1: +bias f32  2: relu(+bias) -> fp16 C16  4: raw partial f32
#define BKK 64
#define ASTH 72                         // smem pitch in halfs (144 B, ldsm conflict-free)
#define NSTG 3

template<int BN>
__device__ __forceinline__ void load_slab_h(const __half* __restrict__ A,
                                            const __half* __restrict__ B,
                                            int Nc, int lda, int kend,
                                            int bm, int bn, int k0,
                                            uint32_t sA, uint32_t sB, int tid) {
#pragma unroll
    for (int i = 0; i < 4; i++) {                  // A: 128 rows x 64 k
        int c = tid + i * 256;
        int row = c >> 3;
        int kc = (c & 7) * 8;
        int gk = k0 + kc;
        uint32_t off = sA + (uint32_t)(row * ASTH + kc) * 2;
        if (gk < kend) cpa16(off, A + (size_t)(bm + row) * lda + gk);
        else           zfill16(off);
    }
#pragma unroll
    for (int i = 0; i < BN / 32; i++) {            // B: BN n-rows x 64 k
        int c = tid + i * 256;
        int row = c >> 3;
        int kc = (c & 7) * 8;
        int gk = k0 + kc;
        uint32_t off = sB + (uint32_t)(row * ASTH + kc) * 2;
        if (gk < kend && (bn + row) < Nc) cpa16(off, B + (size_t)(bn + row) * lda + gk);
        else                              zfill16(off);
    }
}

template<int BN>
__global__ void __launch_bounds__(256, 2)
hgemm_k(const __half* __restrict__ A,
        const __half* __restrict__ B0, const __half* __restrict__ B1,
        const __half* __restrict__ B2,
        const float* __restrict__ bias,
        float* __restrict__ C, __half* __restrict__ C16,
        int Nc, int K, int lda, int ldc, int zoff, int mode, int kchunk) {
    constexpr int NT = BN / 32;                 // n-subtiles per warp
    constexpr int WNT = NT * 8;                 // warp n-tile
    constexpr int STG_H = (128 + BN) * ASTH;

    extern __shared__ __half smh[];

    int z = blockIdx.z;
    const __half* Bm;
    int coff, kb, ke;
    size_t rowoff;
    if (kchunk > 0) {
        Bm = B0; coff = 0;
        kb = z * kchunk;
        ke = min(K, kb + kchunk);
        rowoff = (size_t)z * MM;
    } else {
        Bm = (z == 0) ? B0 : ((z == 1) ? B1 : B2);
        coff = z * zoff;
        kb = 0; ke = K;
        rowoff = 0;
    }

    int tid = threadIdx.x;
    int bn = blockIdx.x * BN, bm = blockIdx.y * 128;
    int warp = tid >> 5, lane = tid & 31;
    int wm = warp >> 2, wn = warp & 3;          // 2 x 4 warp grid
    int g = lane >> 2, tig = lane & 3;

    int lrow = lane & 15;
    int koff8 = (lane & 16) ? 8 : 0;
    int l8 = lane & 7;
    int koff8b = (lane & 8) ? 8 : 0;

    uint32_t sbase = smem_u32(smh);

    float acc[4][NT][4];
#pragma unroll
    for (int mt = 0; mt < 4; mt++)
#pragma unroll
        for (int nt = 0; nt < NT; nt++)
#pragma unroll
            for (int j = 0; j < 4; j++) acc[mt][nt][j] = 0.f;

    const int NS = (ke - kb + BKK - 1) / BKK;

    // prologue: stages 0,1 in flight
#pragma unroll
    for (int s = 0; s < 2; s++) {
        if (s < NS)
            load_slab_h<BN>(A, Bm, Nc, lda, ke, bm, bn, kb + s * BKK,
                            sbase + (uint32_t)(s * STG_H) * 2,
                            sbase + (uint32_t)(s * STG_H + 128 * ASTH) * 2, tid);
        asm volatile("cp.async.commit_group;" ::: "memory");
    }
    asm volatile("cp.async.wait_group 1;" ::: "memory");   // stage 0 ready
    __syncthreads();

    int cst = 0, lst = 2;

    for (int ksl = 0; ksl < NS; ksl++) {
        uint32_t sA = sbase + (uint32_t)(cst * STG_H) * 2;
        uint32_t sB = sA + (uint32_t)(128 * ASTH) * 2;
        uint32_t aw = sA + (uint32_t)((wm * 64 + lrow) * ASTH + koff8) * 2;
        uint32_t bw = sB + (uint32_t)((wn * WNT + lrow) * ASTH + koff8) * 2;
        uint32_t bw2 = sB + (uint32_t)((wn * WNT + 16 + l8) * ASTH + koff8b) * 2;

        // compute this slab: 4 k-slices of 16
#pragma unroll
        for (int ks = 0; ks < 4; ks++) {
            uint32_t kb2 = (uint32_t)(ks * 16) * 2;
            uint32_t a[4][4];
#pragma unroll
            for (int mt = 0; mt < 4; mt++)
                ldsm4(a[mt], aw + (uint32_t)(mt * 16 * ASTH) * 2 + kb2);

            uint32_t bcol[NT][2];
            if (BN == 128) {
                uint32_t b0[4], b1[4];
                ldsm4(b0, bw + kb2);
                ldsm4(b1, bw + (uint32_t)(16 * ASTH) * 2 + kb2);
                bcol[0][0] = b0[0]; bcol[0][1] = b0[2];
                bcol[1][0] = b0[1]; bcol[1][1] = b0[3];
                bcol[2][0] = b1[0]; bcol[2][1] = b1[2];
                bcol[NT - 1][0] = b1[1]; bcol[NT - 1][1] = b1[3];
            } else {
                uint32_t b0[4], b1[2];
                ldsm4(b0, bw + kb2);
                ldsm2(b1, bw2 + kb2);
                bcol[0][0] = b0[0]; bcol[0][1] = b0[2];
                bcol[1][0] = b0[1]; bcol[1][1] = b0[3];
                bcol[NT - 1][0] = b1[0]; bcol[NT - 1][1] = b1[1];
            }
#pragma unroll
            for (int mt = 0; mt < 4; mt++)
#pragma unroll
                for (int nt = 0; nt < NT; nt++)
                    mma_f16(acc[mt][nt], a[mt], bcol[nt]);
        }

        // issue loads for slab ksl+2 (buffer consumed at ksl-1; barrier-separated)
        if (ksl + 2 < NS)
            load_slab_h<BN>(A, Bm, Nc, lda, ke, bm, bn, kb + (ksl + 2) * BKK,
                            sbase + (uint32_t)(lst * STG_H) * 2,
                            sbase + (uint32_t)(lst * STG_H + 128 * ASTH) * 2, tid);
        asm volatile("cp.async.commit_group;" ::: "memory");
        asm volatile("cp.async.wait_group 1;" ::: "memory");  // stage ksl+1 ready
        __syncthreads();

        if (++cst == NSTG) cst = 0;
        if (++lst == NSTG) lst = 0;
    }

    // epilogue
    bool fullN = (bn + BN) <= Nc;
#pragma unroll
    for (int mt = 0; mt < 4; mt++) {
        size_t r0 = rowoff + bm + wm * 64 + mt * 16 + g;
        size_t r1 = r0 + 8;
#pragma unroll
        for (int nt = 0; nt < NT; nt++) {
            int lcol = bn + wn * WNT + nt * 8 + 2 * tig;
            int col = coff + lcol;
            float v0 = acc[mt][nt][0], v1 = acc[mt][nt][1];
            float v2 = acc[mt][nt][2], v3 = acc[mt][nt][3];
            if (fullN) {
                if (mode == 1 || mode == 2) {
                    float2 bb = *(const float2*)(bias + lcol);
                    v0 += bb.x; v1 += bb.y; v2 += bb.x; v3 += bb.y;
                }
                if (mode == 2) {
                    __half2 h0 = __halves2half2(__float2half_rn(fmaxf(v0, 0.f)),
                                                __float2half_rn(fmaxf(v1, 0.f)));
                    __half2 h1 = __halves2half2(__float2half_rn(fmaxf(v2, 0.f)),
                                                __float2half_rn(fmaxf(v3, 0.f)));
                    *(__half2*)(C16 + r0 * ldc + col) = h0;
                    *(__half2*)(C16 + r1 * ldc + col) = h1;
                } else {
                    *(float2*)(C + r0 * ldc + col) = make_float2(v0, v1);
                    *(float2*)(C + r1 * ldc + col) = make_float2(v2, v3);
                }
            } else {
                float vv[4] = {v0, v1, v2, v3};
                size_t rr[4] = {r0, r0, r1, r1};
                int cc[4] = {lcol, lcol + 1, lcol, lcol + 1};
#pragma unroll
                for (int j = 0; j < 4; j++) {
                    if (cc[j] >= Nc) continue;
                    float v = vv[j];
                    if (mode == 1 || mode == 2) v += bias[cc[j]];
                    if (mode == 2)
                        C16[rr[j] * ldc + coff + cc[j]] = __float2half_rn(fmaxf(v, 0.f));
                    else
                        C[rr[j] * ldc + coff + cc[j]] = v;
                }
            }
        }
    }
}

#define DS128 (NSTG * (128 + 128) * ASTH * 2)   // 110592 B
#define DS96  (NSTG * (128 + 96)  * ASTH * 2)   // 96768 B

// ---------------- attention (qkv f32 packed [MM,3360]) -> att16 fp16 ----------------
__global__ void __launch_bounds__(128)
attn_k(const float* __restrict__ qkv, __half* __restrict__ att) {
    __shared__ float ks[TT][HS + 1];
    __shared__ float vs[TT][HS + 1];

    int bh = blockIdx.x;
    int b = bh / NH, h = bh % NH;
    int t = threadIdx.x;
    const size_t rbase = (size_t)b * TT * QKVN;
    const int hoff = h * HS;

    for (int idx = t; idx < TT * HS; idx += 128) {
        int s = idx / HS, d = idx % HS;
        ks[s][d] = qkv[rbase + (size_t)s * QKVN + HH + hoff + d];
        vs[s][d] = qkv[rbase + (size_t)s * QKVN + 2 * HH + hoff + d];
    }
    __syncthreads();

    float qreg[HS];
#pragma unroll
    for (int d = 0; d < HS; d++)
        qreg[d] = qkv[rbase + (size_t)t * QKVN + hoff + d];

    float m = -1e30f, l = 0.f;
    float out[HS];
#pragma unroll
    for (int d = 0; d < HS; d++) out[d] = 0.f;

    for (int s = 0; s <= t; s++) {
        float dot = 0.f;
#pragma unroll
        for (int d = 0; d < HS; d++)
            dot = fmaf(qreg[d], ks[s][d], dot);
        float sc = dot * ATT_SCALE;
        float mn = fmaxf(m, sc);
        float corr = expf(m - mn);
        float p = expf(sc - mn);
        l = l * corr + p;
#pragma unroll
        for (int d = 0; d < HS; d++)
            out[d] = out[d] * corr + p * vs[s][d];
        m = mn;
    }
    float inv = 1.f / l;
    size_t obase = (size_t)(b * TT + t) * HH + hoff;
#pragma unroll
    for (int d = 0; d < HS; d++)
        att[obase + d] = __float2half_rn(out[d] * inv);
}

// ---------------- launcher ----------------
extern "C" void kernel_launch(void* const* d_in, const int* in_sizes, int n_in,
                              void* d_out, int out_size) {
    (void)in_sizes; (void)n_in; (void)out_size;
    const int*   index = (const int*)  d_in[0];
    const float* tok   = (const float*)d_in[1];
    const float* pos   = (const float*)d_in[2];
    const float* wq    = (const float*)d_in[3];
    const float* wk    = (const float*)d_in[4];
    const float* wv    = (const float*)d_in[5];
    const float* wo    = (const float*)d_in[6];
    const float* bo    = (const float*)d_in[7];
    const float* ln1g  = (const float*)d_in[8];
    const float* ln1b  = (const float*)d_in[9];
    const float* ln2g  = (const float*)d_in[10];
    const float* ln2b  = (const float*)d_in[11];
    const float* w1    = (const float*)d_in[12];
    const float* b1    = (const float*)d_in[13];
    const float* w2    = (const float*)d_in[14];
    const float* b2    = (const float*)d_in[15];
    const float* lnfg  = (const float*)d_in[16];
    const float* lnfb  = (const float*)d_in[17];
    const float* wh    = (const float*)d_in[18];
    const float* bh    = (const float*)d_in[19];
    float* out = (float*)d_out;

    float *x, *qkv, *part;
    __half *y16, *att16, *h16, *w16;
    cudaGetSymbolAddress((void**)&x,     g_x);
    cudaGetSymbolAddress((void**)&qkv,   g_qkv);
    cudaGetSymbolAddress((void**)&part,  g_part);
    cudaGetSymbolAddress((void**)&y16,   g_y16);
    cudaGetSymbolAddress((void**)&att16, g_att16);
    cudaGetSymbolAddress((void**)&h16,   g_h16);
    cudaGetSymbolAddress((void**)&w16,   g_w16);

    cudaFuncSetAttribute(hgemm_k<128>, cudaFuncAttributeMaxDynamicSharedMemorySize, DS128);
    cudaFuncSetAttribute(hgemm_k<96>,  cudaFuncAttributeMaxDynamicSharedMemorySize, DS96);

    dim3 tb(32, 8);

    detect_k<<<1, 256>>>(index);

    // ---- convert all weights: f32 [K][N] -> fp16 [N][KPad], once per launch ----
    convT_k<<<dim3(35, 18, NL), tb>>>(wq, w16 + OFF_QKV,            EDIM, HH, KP,
                                      (size_t)EDIM * HH, (size_t)3 * SZQ);
    convT_k<<<dim3(35, 18, NL), tb>>>(wk, w16 + OFF_QKV + SZQ,      EDIM, HH, KP,
                                      (size_t)EDIM * HH, (size_t)3 * SZQ);
    convT_k<<<dim3(35, 18, NL), tb>>>(wv, w16 + OFF_QKV + 2 * SZQ,  EDIM, HH, KP,
                                      (size_t)EDIM * HH, (size_t)3 * SZQ);
    convT_k<<<dim3(36, 18, NL), tb>>>(wo, w16 + OFF_WO,             HH, EDIM, HH,
                                      (size_t)HH * EDIM, (size_t)SZWO);
    convT_k<<<dim3(143, 18, NL), tb>>>(w1, w16 + OFF_W1,            EDIM, FF, KP,
                                      (size_t)EDIM * FF, (size_t)SZW1);
    convT_k<<<dim3(36, 72, NL), tb>>>(w2, w16 + OFF_W2,             FF, EDIM, FF,
                                      (size_t)FF * EDIM, (size_t)SZW2);
    convT_k<<<dim3(1407, 18, 1), tb>>>(wh, w16 + OFF_WH,            EDIM, VOC, KP,
                                      0, 0);

    embed_ln_k<<<MM, 256>>>(index, tok, pos, ln1g, ln1b, x, y16);

    for (int l = 0; l < NL; l++) {
        const __half* pq  = w16 + OFF_QKV + (size_t)l * 3 * SZQ;   // [3360][KP] contiguous
        const __half* po  = w16 + OFF_WO + (size_t)l * SZWO;
        const __half* p1  = w16 + OFF_W1 + (size_t)l * SZW1;
        const __half* p2  = w16 + OFF_W2 + (size_t)l * SZW2;
        const float* pbo = bo + (size_t)l * EDIM;
        const float* g2  = ln2g + (size_t)l * EDIM;
        const float* be2 = ln2b + (size_t)l * EDIM;
        const float* pb1 = b1 + (size_t)l * FF;
        const float* pb2 = b2 + (size_t)l * EDIM;
        const float* gn  = (l + 1 < NL) ? ln1g + (size_t)(l + 1) * EDIM : lnfg;
        const float* bn_ = (l + 1 < NL) ? ln1b + (size_t)(l + 1) * EDIM : lnfb;

        // QKV: single GEMM N=3360 with BN=96 tiles (280 CTAs, 95% wave fill)
        hgemm_k<96><<<dim3(35, 8, 1), 256, DS96>>>(
            y16, pq, nullptr, nullptr, nullptr, qkv, nullptr,
            QKVN, KP, KP, QKVN, 0, 0, 0);

        attn_k<<<BB * NH, 128>>>(qkv, att16);

        // wo: split-K x4 partials, then fused reduce+bias+residual+LN2
        hgemm_k<128><<<dim3(9, 8, 4), 256, DS128>>>(
            att16, po, nullptr, nullptr, nullptr, part, nullptr,
            EDIM, HH, HH, EDIM, 0, 4, 280);
        reduce4ln_k<<<MM, 256>>>(part, pbo, x, g2, be2, y16);

        // w1: relu(y @ w1 + b1) -> fp16 h
        hgemm_k<128><<<dim3(36, 8, 1), 256, DS128>>>(
            y16, p1, nullptr, nullptr, pb1, nullptr, h16, FF, KP, KP, FF, 0, 2, 0);

        // w2: split-K x4 partials, then fused reduce+bias+residual+LN (next ln1 / lnf)
        hgemm_k<128><<<dim3(9, 8, 4), 256, DS128>>>(
            h16, p2, nullptr, nullptr, nullptr, part, nullptr,
            EDIM, FF, FF, EDIM, 0, 4, 1152);
        reduce4ln_k<<<MM, 256>>>(part, pb2, x, gn, bn_, y16);
    }

    // head: logits = lnf(x) @ wh + bh
    hgemm_k<128><<<dim3(352, 8, 1), 256, DS128>>>(
        y16, w16 + OFF_WH, nullptr, nullptr, bh, out, nullptr,
        VOC, KP, KP, VOC, 0, 1, 0);
}

// round 10
// speedup vs baseline: 9.3891x; 1.0811x over previous
#include <cuda_runtime.h>
#include <cuda_fp16.h>
#include <cstdint>
#include <math.h>

// ---------------- problem constants ----------------
#define EDIM 1140
#define KP   1144            // EDIM padded to mult of 8 (fp16 16B chunks)
#define HH   1120
#define NH   32
#define HS   35
#define NL   36
#define VOC  45000
#define TT   128
#define BB   8
#define MM   1024
#define FF   4560
#define QKVN 3360
#define ATT_SCALE 0.16903085094570331f

// ---------------- converted-weight layout (fp16, transposed [N][K]) ----------------
#define SZQ  (1120*KP)
#define OFF_QKV ((size_t)0)
#define SZWO (1140*1120)
#define OFF_WO  ((size_t)NL*3*SZQ)
#define SZW1 (4560*KP)
#define OFF_W1  (OFF_WO + (size_t)NL*SZWO)
#define SZW2 (1140*4560)
#define OFF_W2  (OFF_W1 + (size_t)NL*SZW1)
#define OFF_WH  (OFF_W2 + (size_t)NL*SZW2)
#define WTOT    (OFF_WH + (size_t)VOC*KP)

// ---------------- scratch (device globals) ----------------
__device__ float  g_x[MM * EDIM];
__device__ float  g_qkv[MM * QKVN];
__device__ float  g_part[4 * MM * EDIM];
__device__ __half g_y16[MM * KP];
__device__ __half g_att16[MM * HH];
__device__ __half g_h16[MM * FF];
__device__ __half g_w16[WTOT];
__device__ int    g_is64;

// ---------------- helpers ----------------
__device__ __forceinline__ uint32_t smem_u32(const void* p) {
    uint32_t a;
    asm("{ .reg .u64 t; cvta.to.shared.u64 t, %1; cvt.u32.u64 %0, t; }" : "=r"(a) : "l"(p));
    return a;
}
__device__ __forceinline__ void cpa16(uint32_t s, const void* g) {
    asm volatile("cp.async.cg.shared.global [%0], [%1], 16;" :: "r"(s), "l"(g) : "memory");
}
__device__ __forceinline__ void zfill16(uint32_t s) {
    asm volatile("st.shared.v4.b32 [%0], {%1,%1,%1,%1};" :: "r"(s), "r"(0) : "memory");
}
__device__ __forceinline__ void mma_f16(float* d, const uint32_t* a, const uint32_t* b) {
    asm volatile(
        "mma.sync.aligned.m16n8k16.row.col.f32.f16.f16.f32 "
        "{%0,%1,%2,%3}, {%4,%5,%6,%7}, {%8,%9}, {%0,%1,%2,%3};"
        : "+f"(d[0]), "+f"(d[1]), "+f"(d[2]), "+f"(d[3])
        : "r"(a[0]), "r"(a[1]), "r"(a[2]), "r"(a[3]), "r"(b[0]), "r"(b[1]));
}
__device__ __forceinline__ void ldsm4(uint32_t* r, uint32_t a) {
    asm volatile("ldmatrix.sync.aligned.m8n8.x4.shared.b16 {%0,%1,%2,%3}, [%4];"
        : "=r"(r[0]), "=r"(r[1]), "=r"(r[2]), "=r"(r[3]) : "r"(a));
}
__device__ __forceinline__ void ldsm2(uint32_t* r, uint32_t a) {
    asm volatile("ldmatrix.sync.aligned.m8n8.x2.shared.b16 {%0,%1}, [%2];"
        : "=r"(r[0]), "=r"(r[1]) : "r"(a));
}

// ---------------- index dtype detection ----------------
__global__ void detect_k(const int* __restrict__ raw) {
    __shared__ int any;
    if (threadIdx.x == 0) any = 0;
    __syncthreads();
    int local = 0;
    for (int i = threadIdx.x; i < 512; i += blockDim.x)
        if (raw[2 * i + 1] != 0) local = 1;
    if (local) atomicOr(&any, 1);
    __syncthreads();
    if (threadIdx.x == 0) g_is64 = any ? 0 : 1;
}

// ---------------- weight convert: f32 [K][N] -> fp16 [N][KPad] (RN), zero K-pad ----------
// 64k x 32n tiles; float-wide coalesced reads, __half2 coalesced writes.
__global__ void convT_k(const float* __restrict__ in, __half* __restrict__ out,
                        int K, int N, int KPad, size_t inLs, size_t outLs) {
    in  += (size_t)blockIdx.z * inLs;
    out += (size_t)blockIdx.z * outLs;
    __shared__ float t[64][33];
    int bn = blockIdx.x * 32, bk = blockIdx.y * 64;
    int x = threadIdx.x, y = threadIdx.y;
#pragma unroll
    for (int i = 0; i < 64; i += 8) {
        int k = bk + y + i, n = bn + x;
        t[y + i][x] = (k < K && n < N) ? in[(size_t)k * N + n] : 0.f;
    }
    __syncthreads();
#pragma unroll
    for (int i = 0; i < 32; i += 8) {
        int n = bn + y + i;
        int k = bk + 2 * x;
        if (n < N && k < KPad) {
            __half2 h = __halves2half2(__float2half_rn(t[2 * x][y + i]),
                                       __float2half_rn(t[2 * x + 1][y + i]));
            *(__half2*)(out + (size_t)n * KPad + k) = h;
        }
    }
}

// ---------------- block row-LN from smem values -> y16 (fp16, zero-padded to KP) ----------------
__device__ __forceinline__ void row_ln_emit(const float* v, float s, float s2,
                                            const float* g, const float* b,
                                            __half* yrow) {
    __shared__ float sh0[8], sh1[8];
    for (int o = 16; o > 0; o >>= 1) {
        s  += __shfl_down_sync(0xffffffffu, s, o);
        s2 += __shfl_down_sync(0xffffffffu, s2, o);
    }
    int w = threadIdx.x >> 5, lane = threadIdx.x & 31;
    if (lane == 0) { sh0[w] = s; sh1[w] = s2; }
    __syncthreads();
    if (threadIdx.x == 0) {
        float ts = 0.f, ts2 = 0.f;
        for (int i = 0; i < 8; i++) { ts += sh0[i]; ts2 += sh1[i]; }
        float mu = ts / (float)EDIM;
        float var = ts2 / (float)EDIM - mu * mu;
        sh0[0] = mu;
        sh1[0] = rsqrtf(var + 1e-5f);
    }
    __syncthreads();
    float mu = sh0[0], rstd = sh1[0];
    for (int c = threadIdx.x; c < KP; c += blockDim.x) {
        float o = (c < EDIM) ? (v[c] - mu) * rstd * g[c] + b[c] : 0.f;
        yrow[c] = __float2half_rn(o);
    }
}

// ---------------- embedding + LN1(layer0) ----------------
__global__ void embed_ln_k(const int* __restrict__ raw,
                           const float* __restrict__ tok,
                           const float* __restrict__ pos,
                           const float* __restrict__ g,
                           const float* __restrict__ b,
                           float* __restrict__ x, __half* __restrict__ y16) {
    __shared__ float v[EDIM];
    int r = blockIdx.x, t = r % TT;
    int idx = g_is64 ? raw[2 * r] : raw[r];
    const float* te = tok + (size_t)idx * EDIM;
    const float* pe = pos + (size_t)t * EDIM;
    float s = 0.f, s2 = 0.f;
    for (int c = threadIdx.x; c < EDIM; c += blockDim.x) {
        float val = te[c] + pe[c];
        v[c] = val;
        x[(size_t)r * EDIM + c] = val;
        s += val; s2 = fmaf(val, val, s2);
    }
    __syncthreads();
    row_ln_emit(v, s, s2, g, b, y16 + (size_t)r * KP);
}

// ---------------- split-K reduce + residual + bias -> x; then LN -> y16 (float4) -------------
__global__ void reduce4ln_k(const float* __restrict__ part,
                            const float* __restrict__ bias,
                            float* __restrict__ x,
                            const float* __restrict__ g,
                            const float* __restrict__ b,
                            __half* __restrict__ y16) {
    __shared__ float v[EDIM];
    int r = blockIdx.x;
    const float4* p0 = (const float4*)(part + (size_t)r * EDIM);
    const float4* p1 = (const float4*)(part + (size_t)MM * EDIM + (size_t)r * EDIM);
    const float4* p2 = (const float4*)(part + (size_t)2 * MM * EDIM + (size_t)r * EDIM);
    const float4* p3 = (const float4*)(part + (size_t)3 * MM * EDIM + (size_t)r * EDIM);
    const float4* bb = (const float4*)bias;
    float4* xr = (float4*)(x + (size_t)r * EDIM);
    float s = 0.f, s2 = 0.f;
    for (int c = threadIdx.x; c < EDIM / 4; c += blockDim.x) {
        float4 a0 = p0[c], a1 = p1[c], a2 = p2[c], a3 = p3[c];
        float4 bv = bb[c], xv = xr[c];
        float4 val;
        val.x = ((a0.x + a1.x) + (a2.x + a3.x)) + bv.x + xv.x;
        val.y = ((a0.y + a1.y) + (a2.y + a3.y)) + bv.y + xv.y;
        val.z = ((a0.z + a1.z) + (a2.z + a3.z)) + bv.z + xv.z;
        val.w = ((a0.w + a1.w) + (a2.w + a3.w)) + bv.w + xv.w;
        xr[c] = val;
        *(float4*)(v + 4 * c) = val;
        s += val.x + val.y + val.z + val.w;
        s2 = fmaf(val.x, val.x, s2);
        s2 = fmaf(val.y, val.y, s2);
        s2 = fmaf(val.z, val.z, s2);
        s2 = fmaf(val.w, val.w, s2);
    }
    __syncthreads();
    row_ln_emit(v, s, s2, g, b, y16 + (size_t)r * KP);
}

// ---------------- fp16 tensor-core GEMM (BKK=64, 3-stage), templated on BN ----------------
#define BKK 64
#define ASTH 72                         // smem pitch in halfs (144 B, ldsm conflict-free)
#define NSTG 3

template<int BN>
__device__ __forceinline__ void load_slab_h(const __half* __restrict__ A,
                                            const __half* __restrict__ B,
                                            int Nc, int lda, int kend,
                                            int bm, int bn, int k0,
                                            uint32_t sA, uint32_t sB, int tid) {
#pragma unroll
    for (int i = 0; i < 4; i++) {                  // A: 128 rows x 64 k
        int c = tid + i * 256;
        int row = c >> 3;
        int kc = (c & 7) * 8;
        int gk = k0 + kc;
        uint32_t off = sA + (uint32_t)(row * ASTH + kc) * 2;
        if (gk < kend) cpa16(off, A + (size_t)(bm + row) * lda + gk);
        else           zfill16(off);
    }
#pragma unroll
    for (int i = 0; i < BN / 32; i++) {            // B: BN n-rows x 64 k
        int c = tid + i * 256;
        int row = c >> 3;
        int kc = (c & 7) * 8;
        int gk = k0 + kc;
        uint32_t off = sB + (uint32_t)(row * ASTH + kc) * 2;
        if (gk < kend && (bn + row) < Nc) cpa16(off, B + (size_t)(bn + row) * lda + gk);
        else                              zfill16(off);
    }
}

template<int BN>
__global__ void __launch_bounds__(256, 2)
hgemm_k(const __half* __restrict__ A,
        const __half* __restrict__ B0, const __half* __restrict__ B1,
        const __half* __restrict__ B2,
        const float* __restrict__ bias,
        float* __restrict__ C, __half* __restrict__ C16,
        int Nc, int K, int lda, int ldc, int zoff, int mode, int kchunk) {
    constexpr int NT = BN / 32;                 // n-subtiles per warp
    constexpr int WNT = NT * 8;                 // warp n-tile
    constexpr int STG_H = (128 + BN) * ASTH;

    extern __shared__ __half smh[];

    int z = blockIdx.z;
    const __half* Bm;
    int coff, kb, ke;
    size_t rowoff;
    if (kchunk > 0) {
        Bm = B0; coff = 0;
        kb = z * kchunk;
        ke = min(K, kb + kchunk);
        rowoff = (size_t)z * MM;
    } else {
        Bm = (z == 0) ? B0 : ((z == 1) ? B1 : B2);
        coff = z * zoff;
        kb = 0; ke = K;
        rowoff = 0;
    }

    int tid = threadIdx.x;
    int bn = blockIdx.x * BN, bm = blockIdx.y * 128;
    int warp = tid >> 5, lane = tid & 31;
    int wm = warp >> 2, wn = warp & 3;          // 2 x 4 warp grid
    int g = lane >> 2, tig = lane & 3;

    int lrow = lane & 15;
    int koff8 = (lane & 16) ? 8 : 0;
    int l8 = lane & 7;
    int koff8b = (lane & 8) ? 8 : 0;

    uint32_t sbase = smem_u32(smh);

    float acc[4][NT][4];
#pragma unroll
    for (int mt = 0; mt < 4; mt++)
#pragma unroll
        for (int nt = 0; nt < NT; nt++)
#pragma unroll
            for (int j = 0; j < 4; j++) acc[mt][nt][j] = 0.f;

    const int NS = (ke - kb + BKK - 1) / BKK;

    // prologue: stages 0,1 in flight
#pragma unroll
    for (int s = 0; s < 2; s++) {
        if (s < NS)
            load_slab_h<BN>(A, Bm, Nc, lda, ke, bm, bn, kb + s * BKK,
                            sbase + (uint32_t)(s * STG_H) * 2,
                            sbase + (uint32_t)(s * STG_H + 128 * ASTH) * 2, tid);
        asm volatile("cp.async.commit_group;" ::: "memory");
    }
    asm volatile("cp.async.wait_group 1;" ::: "memory");   // stage 0 ready
    __syncthreads();

    int cst = 0, lst = 2;

    for (int ksl = 0; ksl < NS; ksl++) {
        uint32_t sA = sbase + (uint32_t)(cst * STG_H) * 2;
        uint32_t sB = sA + (uint32_t)(128 * ASTH) * 2;
        uint32_t aw = sA + (uint32_t)((wm * 64 + lrow) * ASTH + koff8) * 2;
        uint32_t bw = sB + (uint32_t)((wn * WNT + lrow) * ASTH + koff8) * 2;
        uint32_t bw2 = sB + (uint32_t)((wn * WNT + 16 + l8) * ASTH + koff8b) * 2;

        // compute this slab: 4 k-slices of 16
#pragma unroll
        for (int ks = 0; ks < 4; ks++) {
            uint32_t kb2 = (uint32_t)(ks * 16) * 2;
            uint32_t a[4][4];
#pragma unroll
            for (int mt = 0; mt < 4; mt++)
                ldsm4(a[mt], aw + (uint32_t)(mt * 16 * ASTH) * 2 + kb2);

            uint32_t bcol[NT][2];
            if (BN == 128) {
                uint32_t b0[4], b1[4];
                ldsm4(b0, bw + kb2);
                ldsm4(b1, bw + (uint32_t)(16 * ASTH) * 2 + kb2);
                bcol[0][0] = b0[0]; bcol[0][1] = b0[2];
                bcol[1][0] = b0[1]; bcol[1][1] = b0[3];
                bcol[2][0] = b1[0]; bcol[2][1] = b1[2];
                bcol[NT - 1][0] = b1[1]; bcol[NT - 1][1] = b1[3];
            } else {
                uint32_t b0[4], b1[2];
                ldsm4(b0, bw + kb2);
                ldsm2(b1, bw2 + kb2);
                bcol[0][0] = b0[0]; bcol[0][1] = b0[2];
                bcol[1][0] = b0[1]; bcol[1][1] = b0[3];
                bcol[NT - 1][0] = b1[0]; bcol[NT - 1][1] = b1[1];
            }
#pragma unroll
            for (int mt = 0; mt < 4; mt++)
#pragma unroll
                for (int nt = 0; nt < NT; nt++)
                    mma_f16(acc[mt][nt], a[mt], bcol[nt]);
        }

        // issue loads for slab ksl+2 (buffer consumed at ksl-1; barrier-separated)
        if (ksl + 2 < NS)
            load_slab_h<BN>(A, Bm, Nc, lda, ke, bm, bn, kb + (ksl + 2) * BKK,
                            sbase + (uint32_t)(lst * STG_H) * 2,
                            sbase + (uint32_t)(lst * STG_H + 128 * ASTH) * 2, tid);
        asm volatile("cp.async.commit_group;" ::: "memory");
        asm volatile("cp.async.wait_group 1;" ::: "memory");  // stage ksl+1 ready
        __syncthreads();

        if (++cst == NSTG) cst = 0;
        if (++lst == NSTG) lst = 0;
    }

    // epilogue
    bool fullN = (bn + BN) <= Nc;
#pragma unroll
    for (int mt = 0; mt < 4; mt++) {
        size_t r0 = rowoff + bm + wm * 64 + mt * 16 + g;
        size_t r1 = r0 + 8;
#pragma unroll
        for (int nt = 0; nt < NT; nt++) {
            int lcol = bn + wn * WNT + nt * 8 + 2 * tig;
            int col = coff + lcol;
            float v0 = acc[mt][nt][0], v1 = acc[mt][nt][1];
            float v2 = acc[mt][nt][2], v3 = acc[mt][nt][3];
            if (fullN) {
                if (mode == 1 || mode == 2) {
                    float2 bb = *(const float2*)(bias + lcol);
                    v0 += bb.x; v1 += bb.y; v2 += bb.x; v3 += bb.y;
                }
                if (mode == 2) {
                    __half2 h0 = __halves2half2(__float2half_rn(fmaxf(v0, 0.f)),
                                                __float2half_rn(fmaxf(v1, 0.f)));
                    __half2 h1 = __halves2half2(__float2half_rn(fmaxf(v2, 0.f)),
                                                __float2half_rn(fmaxf(v3, 0.f)));
                    *(__half2*)(C16 + r0 * ldc + col) = h0;
                    *(__half2*)(C16 + r1 * ldc + col) = h1;
                } else {
                    *(float2*)(C + r0 * ldc + col) = make_float2(v0, v1);
                    *(float2*)(C + r1 * ldc + col) = make_float2(v2, v3);
                }
            } else {
                float vv[4] = {v0, v1, v2, v3};
                size_t rr[4] = {r0, r0, r1, r1};
                int cc[4] = {lcol, lcol + 1, lcol, lcol + 1};
#pragma unroll
                for (int j = 0; j < 4; j++) {
                    if (cc[j] >= Nc) continue;
                    float v = vv[j];
                    if (mode == 1 || mode == 2) v += bias[cc[j]];
                    if (mode == 2)
                        C16[rr[j] * ldc + coff + cc[j]] = __float2half_rn(fmaxf(v, 0.f));
                    else
                        C[rr[j] * ldc + coff + cc[j]] = v;
                }
            }
        }
    }
}

#define DS128 (NSTG * (128 + 128) * ASTH * 2)   // 110592 B
#define DS96  (NSTG * (128 + 96)  * ASTH * 2)   // 96768 B

// ---------------- attention: 8-way split over s per query, shfl merge ----------------
// grid (BB*NH, 8); block 128. Block y handles queries t in [16y, 16y+16).
// Thread: query t = 16y + (tid>>3), lane-slice sub = tid&7 processes s = sub, sub+8, ...
// Exact softmax merge over the 8 lanes (same products, reassociated sums only).
__global__ void __launch_bounds__(128)
attn_k(const float* __restrict__ qkv, __half* __restrict__ att) {
    __shared__ float ks[TT][HS + 1];
    __shared__ float vs[TT][HS + 1];

    int bh = blockIdx.x;
    int b = bh / NH, h = bh % NH;
    int qy = blockIdx.y;
    int tid = threadIdx.x;
    int t = qy * 16 + (tid >> 3);
    int sub = tid & 7;
    const size_t rbase = (size_t)b * TT * QKVN;
    const int hoff = h * HS;
    const int rows = qy * 16 + 16;      // causal: only K/V rows <= max query

    for (int idx = tid; idx < rows * HS; idx += 128) {
        int s = idx / HS, d = idx % HS;
        ks[s][d] = qkv[rbase + (size_t)s * QKVN + HH + hoff + d];
        vs[s][d] = qkv[rbase + (size_t)s * QKVN + 2 * HH + hoff + d];
    }
    __syncthreads();

    float qreg[HS];
#pragma unroll
    for (int d = 0; d < HS; d++)
        qreg[d] = qkv[rbase + (size_t)t * QKVN + hoff + d];

    float m = -1e30f, l = 0.f;
    float out[HS];
#pragma unroll
    for (int d = 0; d < HS; d++) out[d] = 0.f;

    for (int s = sub; s <= t; s += 8) {
        float dot = 0.f;
#pragma unroll
        for (int d = 0; d < HS; d++)
            dot = fmaf(qreg[d], ks[s][d], dot);
        float sc = dot * ATT_SCALE;
        float mn = fmaxf(m, sc);
        float corr = expf(m - mn);
        float p = expf(sc - mn);
        l = l * corr + p;
#pragma unroll
        for (int d = 0; d < HS; d++)
            out[d] = out[d] * corr + p * vs[s][d];
        m = mn;
    }

    // merge the 8 lane-slices of this query (lanes 8q..8q+7 within the warp)
    float M = m;
#pragma unroll
    for (int o = 1; o < 8; o <<= 1)
        M = fmaxf(M, __shfl_xor_sync(0xffffffffu, M, o));
    float e = expf(m - M);              // lanes with no work: m=-1e30 -> e=0
    float ls = l * e;
#pragma unroll
    for (int o = 1; o < 8; o <<= 1)
        ls += __shfl_xor_sync(0xffffffffu, ls, o);
    float inv = 1.f / ls;

    size_t obase = (size_t)(b * TT + t) * HH + hoff;
#pragma unroll
    for (int d = 0; d < HS; d++) {
        float ov = out[d] * e;
#pragma unroll
        for (int o2 = 1; o2 < 8; o2 <<= 1)
            ov += __shfl_xor_sync(0xffffffffu, ov, o2);
        if (sub == 0) att[obase + d] = __float2half_rn(ov * inv);
    }
}

// ---------------- launcher ----------------
extern "C" void kernel_launch(void* const* d_in, const int* in_sizes, int n_in,
                              void* d_out, int out_size) {
    (void)in_sizes; (void)n_in; (void)out_size;
    const int*   index = (const int*)  d_in[0];
    const float* tok   = (const float*)d_in[1];
    const float* pos   = (const float*)d_in[2];
    const float* wq    = (const float*)d_in[3];
    const float* wk    = (const float*)d_in[4];
    const float* wv    = (const float*)d_in[5];
    const float* wo    = (const float*)d_in[6];
    const float* bo    = (const float*)d_in[7];
    const float* ln1g  = (const float*)d_in[8];
    const float* ln1b  = (const float*)d_in[9];
    const float* ln2g  = (const float*)d_in[10];
    const float* ln2b  = (const float*)d_in[11];
    const float* w1    = (const float*)d_in[12];
    const float* b1    = (const float*)d_in[13];
    const float* w2    = (const float*)d_in[14];
    const float* b2    = (const float*)d_in[15];
    const float* lnfg  = (const float*)d_in[16];
    const float* lnfb  = (const float*)d_in[17];
    const float* wh    = (const float*)d_in[18];
    const float* bh    = (const float*)d_in[19];
    float* out = (float*)d_out;

    float *x, *qkv, *part;
    __half *y16, *att16, *h16, *w16;
    cudaGetSymbolAddress((void**)&x,     g_x);
    cudaGetSymbolAddress((void**)&qkv,   g_qkv);
    cudaGetSymbolAddress((void**)&part,  g_part);
    cudaGetSymbolAddress((void**)&y16,   g_y16);
    cudaGetSymbolAddress((void**)&att16, g_att16);
    cudaGetSymbolAddress((void**)&h16,   g_h16);
    cudaGetSymbolAddress((void**)&w16,   g_w16);

    cudaFuncSetAttribute(hgemm_k<128>, cudaFuncAttributeMaxDynamicSharedMemorySize, DS128);
    cudaFuncSetAttribute(hgemm_k<96>,  cudaFuncAttributeMaxDynamicSharedMemorySize, DS96);

    dim3 tb(32, 8);

    detect_k<<<1, 256>>>(index);

    // ---- convert all weights: f32 [K][N] -> fp16 [N][KPad], once per launch ----
    convT_k<<<dim3(35, 18, NL), tb>>>(wq, w16 + OFF_QKV,            EDIM, HH, KP,
                                      (size_t)EDIM * HH, (size_t)3 * SZQ);
    convT_k<<<dim3(35, 18, NL), tb>>>(wk, w16 + OFF_QKV + SZQ,      EDIM, HH, KP,
                                      (size_t)EDIM * HH, (size_t)3 * SZQ);
    convT_k<<<dim3(35, 18, NL), tb>>>(wv, w16 + OFF_QKV + 2 * SZQ,  EDIM, HH, KP,
                                      (size_t)EDIM * HH, (size_t)3 * SZQ);
    convT_k<<<dim3(36, 18, NL), tb>>>(wo, w16 + OFF_WO,             HH, EDIM, HH,
                                      (size_t)HH * EDIM, (size_t)SZWO);
    convT_k<<<dim3(143, 18, NL), tb>>>(w1, w16 + OFF_W1,            EDIM, FF, KP,
                                      (size_t)EDIM * FF, (size_t)SZW1);
    convT_k<<<dim3(36, 72, NL), tb>>>(w2, w16 + OFF_W2,             FF, EDIM, FF,
                                      (size_t)FF * EDIM, (size_t)SZW2);
    convT_k<<<dim3(1407, 18, 1), tb>>>(wh, w16 + OFF_WH,            EDIM, VOC, KP,
                                      0, 0);

    embed_ln_k<<<MM, 256>>>(index, tok, pos, ln1g, ln1b, x, y16);

    for (int l = 0; l < NL; l++) {
        const __half* pq  = w16 + OFF_QKV + (size_t)l * 3 * SZQ;   // [3360][KP] contiguous
        const __half* po  = w16 + OFF_WO + (size_t)l * SZWO;
        const __half* p1  = w16 + OFF_W1 + (size_t)l * SZW1;
        const __half* p2  = w16 + OFF_W2 + (size_t)l * SZW2;
        const float* pbo = bo + (size_t)l * EDIM;
        const float* g2  = ln2g + (size_t)l * EDIM;
        const float* be2 = ln2b + (size_t)l * EDIM;
        const float* pb1 = b1 + (size_t)l * FF;
        const float* pb2 = b2 + (size_t)l * EDIM;
        const float* gn  = (l + 1 < NL) ? ln1g + (size_t)(l + 1) * EDIM : lnfg;
        const float* bn_ = (l + 1 < NL) ? ln1b + (size_t)(l + 1) * EDIM : lnfb;

        // QKV: single GEMM N=3360 with BN=96 tiles (280 CTAs, 95% wave fill)
        hgemm_k<96><<<dim3(35, 8, 1), 256, DS96>>>(
            y16, pq, nullptr, nullptr, nullptr, qkv, nullptr,
            QKVN, KP, KP, QKVN, 0, 0, 0);

        attn_k<<<dim3(BB * NH, 8), 128>>>(qkv, att16);

        // wo: split-K x4 partials, then fused reduce+bias+residual+LN2
        hgemm_k<128><<<dim3(9, 8, 4), 256, DS128>>>(
            att16, po, nullptr, nullptr, nullptr, part, nullptr,
            EDIM, HH, HH, EDIM, 0, 4, 280);
        reduce4ln_k<<<MM, 256>>>(part, pbo, x, g2, be2, y16);

        // w1: relu(y @ w1 + b1) -> fp16 h
        hgemm_k<128><<<dim3(36, 8, 1), 256, DS128>>>(
            y16, p1, nullptr, nullptr, pb1, nullptr, h16, FF, KP, KP, FF, 0, 2, 0);

        // w2: split-K x4 partials, then fused reduce+bias+residual+LN (next ln1 / lnf)
        hgemm_k<128><<<dim3(9, 8, 4), 256, DS128>>>(
            h16, p2, nullptr, nullptr, nullptr, part, nullptr,
            EDIM, FF, FF, EDIM, 0, 4, 1152);
        reduce4ln_k<<<MM, 256>>>(part, pb2, x, gn, bn_, y16);
    }

    // head: logits = lnf(x) @ wh + bh
    hgemm_k<128><<<dim3(352, 8, 1), 256, DS128>>>(
        y16, w16 + OFF_WH, nullptr, nullptr, bh, out, nullptr,
        VOC, KP, KP, VOC, 0, 1, 0);
}